// round 5
// baseline (speedup 1.0000x reference)
#include <cuda_runtime.h>
#include <math.h>

// Problem constants
//   B=8, C=128, T=128, F=512, K=64
//   S_lat  = T*K = 8192   positions/batch on latent path
//   S_side = T*F = 65536  positions/batch on side path
static constexpr int SL = 128 * 64;    // 8192
static constexpr int SS = 128 * 512;   // 65536

// ---------------- scratch (device globals; no cudaMalloc allowed) ----------
__device__ float g_rms[8 * 65536];                 // per-position inv-rms (reused)
__device__ float g_lat_h[8 * 128 * 8192];          // latent_h
__device__ float g_kbuf[8 * 128 * 8192];           // k projection
__device__ float g_vbuf[8 * 128 * 8192];           // v projection
__device__ float g_qh[8 * 128 * 65536];            // query_h
__device__ float g_q[8 * 128 * 65536];             // q projection -> attended (in place)
__device__ float g_A[8 * 256 * 65536];             // swiglu intermediate (both MLPs)

// ---------------- RMS: inv_rms per spatial position over C=128 -------------
__global__ void rms_k(const float* __restrict__ X, float* __restrict__ R, int S)
{
    int idx = blockIdx.x * blockDim.x + threadIdx.x;   // < 8*S
    int b = idx / S, m = idx - b * S;
    const float* p = X + (long)b * 128 * S + m;
    float s = 0.f;
#pragma unroll 8
    for (int c = 0; c < 128; c++) { float v = p[(long)c * S]; s = fmaf(v, v, s); }
    R[idx] = rsqrtf(s * (1.f / 128.f) + 1e-6f);
}

// ---------------- GLU: act = a * silu(g), in place on first 128 chans ------
__global__ void glu_k(float* __restrict__ H, int S)
{
    long idx = (long)blockIdx.x * 256 + threadIdx.x;   // total 8*128*S
    long perB = 128L * S;
    int b = (int)(idx / perB);
    long rem = idx - (long)b * perB;                   // c*S + m
    long base = (long)b * 256 * S + rem;
    float a = H[base], g = H[base + 128L * S];
    H[base] = a * (g / (1.f + expf(-g)));
}

// ---------------- generic fp32 GEMM, C(reduction)=128 ----------------------
// Y[b,o,m] = act( sum_c W[o,c] * Xn[b,c,m] + bias[o] ) (+ scale*add[b,o,m])
// Xn = X * rvec[m] * gamma[c] when NORM.
template<bool NORM, bool SILU, bool HASADD>
__global__ void __launch_bounds__(256) gemm_k(
    const float* __restrict__ W, const float* __restrict__ bias,
    const float* __restrict__ X, long xBatch,
    const float* __restrict__ rvec, const float* __restrict__ gamma,
    float* __restrict__ Y, long yBatch,
    const float* __restrict__ addp, const float* __restrict__ addScaleP,
    int S)
{
    const int m0 = blockIdx.x * 64;
    const int oB = blockIdx.y * 64;
    const int b  = blockIdx.z;
    const float* Xb = X + (long)b * xBatch;
    float* Yb = Y + (long)b * yBatch;
    const float* rb = NORM ? (rvec + (long)b * S) : nullptr;

    __shared__ float Ws[16][68];   // W chunk, transposed: Ws[c][o]
    __shared__ float Xs[16][64];   // X chunk: Xs[c][m]

    const int tid = threadIdx.x;
    const int ty = tid >> 4, tx = tid & 15;
    float acc[4][4] = {};

    for (int cc = 0; cc < 128; cc += 16) {
#pragma unroll
        for (int e = 0; e < 4; e++) {
            int lin = tid + e * 256;
            int wr = lin >> 4, wc = lin & 15;                 // wr: o, wc: c
            Ws[wc][wr] = W[(oB + wr) * 128 + cc + wc];
        }
#pragma unroll
        for (int e = 0; e < 4; e++) {
            int lin = tid + e * 256;
            int xr = lin >> 6, xc = lin & 63;                 // xr: c, xc: m
            float v = Xb[(long)(cc + xr) * S + m0 + xc];
            if (NORM) v *= rb[m0 + xc] * gamma[cc + xr];
            Xs[xr][xc] = v;
        }
        __syncthreads();
#pragma unroll
        for (int k = 0; k < 16; k++) {
            float4 af = *(const float4*)&Ws[k][ty * 4];
            float4 bf = *(const float4*)&Xs[k][tx * 4];
            float av[4] = {af.x, af.y, af.z, af.w};
            float bv[4] = {bf.x, bf.y, bf.z, bf.w};
#pragma unroll
            for (int i = 0; i < 4; i++)
#pragma unroll
                for (int j = 0; j < 4; j++)
                    acc[i][j] = fmaf(av[i], bv[j], acc[i][j]);
        }
        __syncthreads();
    }

    float scl = 1.f;
    if (HASADD) { if (addScaleP) scl = __ldg(addScaleP); }
#pragma unroll
    for (int i = 0; i < 4; i++) {
        int o = oB + ty * 4 + i;
        float bi = bias[o];
        long rowoff = (long)o * S + m0 + tx * 4;
        float t0[4];
#pragma unroll
        for (int j = 0; j < 4; j++) {
            float y = acc[i][j] + bi;
            if (SILU) y = y / (1.f + expf(-y));
            t0[j] = y;
        }
        if (HASADD) {
            float4 ad = *(const float4*)&addp[(long)b * yBatch + rowoff];
            t0[0] += scl * ad.x; t0[1] += scl * ad.y;
            t0[2] += scl * ad.z; t0[3] += scl * ad.w;
        }
        float4 o4 = {t0[0], t0[1], t0[2], t0[3]};
        *(float4*)&Yb[rowoff] = o4;
    }
}

// ---------------- fused per-(b,t) cross attention ---------------------------
// scores[f,k] = ss * sum_c q[c,f]*kmat[c,k] + ps * basis[k, f]
// w = softmax_k(scores); attended[c,f] = sum_k w[f,k]*v[c,k]; written over q.
__global__ void __launch_bounds__(256) attn_k(
    float* __restrict__ Q, const float* __restrict__ Kb, const float* __restrict__ Vb,
    const float* __restrict__ basis,
    const float* __restrict__ sscaleP, const float* __restrict__ pscaleP)
{
    extern __shared__ float sm[];
    float* Ks = sm;                  // [128][68]
    float* Qs = Ks + 128 * 68;       // [128][68]
    float* Vs = Qs + 128 * 68;       // [128][65]
    float* Ss = Vs + 128 * 65;       // [64][65]
    const int t = blockIdx.x, b = blockIdx.y;
    const int tid = threadIdx.x;
    const float sscale = __ldg(sscaleP), pscale = __ldg(pscaleP);

    for (int lin = tid; lin < 128 * 64; lin += 256) {
        int c = lin >> 6, kk = lin & 63;
        long g = ((long)(b * 128 + c) * 128 + t) * 64 + kk;
        Ks[c * 68 + kk] = Kb[g];
        Vs[c * 65 + kk] = Vb[g];
    }
    __syncthreads();

    const int ty = tid >> 4, tx = tid & 15;   // scores: 64f x 64k, 4x4/thr
    const int ay = tid >> 4, ax = tid & 15;   // attended: 128c x 64f, 8x4/thr

    for (int f0 = 0; f0 < 512; f0 += 64) {
        for (int lin = tid; lin < 128 * 64; lin += 256) {
            int c = lin >> 6, j = lin & 63;
            Qs[c * 68 + j] = Q[((long)(b * 128 + c) * 128 + t) * 512 + f0 + j];
        }
        __syncthreads();

        // scores GEMM (reduce over c=128)
        float acc[4][4] = {};
#pragma unroll 4
        for (int c = 0; c < 128; c++) {
            float4 af = *(const float4*)&Qs[c * 68 + ty * 4];
            float4 bf = *(const float4*)&Ks[c * 68 + tx * 4];
            float av[4] = {af.x, af.y, af.z, af.w};
            float bv[4] = {bf.x, bf.y, bf.z, bf.w};
#pragma unroll
            for (int i = 0; i < 4; i++)
#pragma unroll
                for (int j = 0; j < 4; j++)
                    acc[i][j] = fmaf(av[i], bv[j], acc[i][j]);
        }
#pragma unroll
        for (int i = 0; i < 4; i++)
#pragma unroll
            for (int j = 0; j < 4; j++) {
                int fl = ty * 4 + i, kk = tx * 4 + j;
                Ss[fl * 65 + kk] = acc[i][j] * sscale
                                 + pscale * basis[kk * 512 + f0 + fl];
            }
        __syncthreads();

        // softmax over kk (64), 4 threads per row
        {
            int row = tid >> 2, q = tid & 3;
            float* r = &Ss[row * 65];
            float mx = -3.4e38f;
            for (int i = q; i < 64; i += 4) mx = fmaxf(mx, r[i]);
            mx = fmaxf(mx, __shfl_xor_sync(0xffffffffu, mx, 1));
            mx = fmaxf(mx, __shfl_xor_sync(0xffffffffu, mx, 2));
            float sum = 0.f;
            for (int i = q; i < 64; i += 4) { float e = expf(r[i] - mx); r[i] = e; sum += e; }
            sum += __shfl_xor_sync(0xffffffffu, sum, 1);
            sum += __shfl_xor_sync(0xffffffffu, sum, 2);
            float inv = 1.f / sum;
            for (int i = q; i < 64; i += 4) r[i] *= inv;
        }
        __syncthreads();

        // attended GEMM (reduce over kk=64), write in place over Q
        float at[8][4] = {};
        for (int kk = 0; kk < 64; kk++) {
            float bv[4];
#pragma unroll
            for (int j = 0; j < 4; j++) bv[j] = Ss[(ax * 4 + j) * 65 + kk];
#pragma unroll
            for (int i = 0; i < 8; i++) {
                float av = Vs[(ay * 8 + i) * 65 + kk];
#pragma unroll
                for (int j = 0; j < 4; j++) at[i][j] = fmaf(av, bv[j], at[i][j]);
            }
        }
#pragma unroll
        for (int i = 0; i < 8; i++) {
            int c = ay * 8 + i;
            float4 o4 = {at[i][0], at[i][1], at[i][2], at[i][3]};
            *(float4*)&Q[((long)(b * 128 + c) * 128 + t) * 512 + f0 + ax * 4] = o4;
        }
        // next iteration's post-load __syncthreads orders Ss reuse
    }
}

// ---------------- launch ----------------------------------------------------
extern "C" void kernel_launch(void* const* d_in, const int* in_sizes, int n_in,
                              void* d_out, int out_size)
{
    const float* latent     = (const float*)d_in[0];
    const float* side       = (const float*)d_in[1];
    const float* basis      = (const float*)d_in[2];
    const float* lp_gamma   = (const float*)d_in[3];
    const float* lp_w       = (const float*)d_in[4];
    const float* lp_b       = (const float*)d_in[5];
    const float* qn_gamma   = (const float*)d_in[6];
    const float* qmlp_in_w  = (const float*)d_in[7];
    const float* qmlp_in_b  = (const float*)d_in[8];
    const float* qmlp_out_w = (const float*)d_in[9];
    const float* qmlp_out_b = (const float*)d_in[10];
    const float* q_w        = (const float*)d_in[11];
    const float* q_b        = (const float*)d_in[12];
    const float* k_w        = (const float*)d_in[13];
    const float* k_b        = (const float*)d_in[14];
    const float* v_w        = (const float*)d_in[15];
    const float* v_b        = (const float*)d_in[16];
    const float* o_w        = (const float*)d_in[17];
    const float* o_b        = (const float*)d_in[18];
    const float* ffn_gamma  = (const float*)d_in[19];
    const float* ffn_in_w   = (const float*)d_in[20];
    const float* ffn_in_b   = (const float*)d_in[21];
    const float* ffn_out_w  = (const float*)d_in[22];
    const float* ffn_out_b  = (const float*)d_in[23];
    const float* score_scale      = (const float*)d_in[24];
    const float* prior_scale      = (const float*)d_in[25];
    const float* query_skip_scale = (const float*)d_in[26];
    float* out = (float*)d_out;

    float *rms_p, *lath_p, *kbuf_p, *vbuf_p, *qh_p, *q_p, *A_p;
    cudaGetSymbolAddress((void**)&rms_p,  g_rms);
    cudaGetSymbolAddress((void**)&lath_p, g_lat_h);
    cudaGetSymbolAddress((void**)&kbuf_p, g_kbuf);
    cudaGetSymbolAddress((void**)&vbuf_p, g_vbuf);
    cudaGetSymbolAddress((void**)&qh_p,   g_qh);
    cudaGetSymbolAddress((void**)&q_p,    g_q);
    cudaGetSymbolAddress((void**)&A_p,    g_A);

    const long LB = 128L * SL;      // latent batch stride
    const long SB = 128L * SS;      // side batch stride
    const long AB = 256L * SS;      // swiglu-intermediate batch stride

    // latent path: rmsnorm -> lp conv -> silu
    rms_k<<<(8 * SL) / 256, 256>>>(latent, rms_p, SL);
    gemm_k<true, true, false><<<dim3(SL / 64, 2, 8), 256>>>(
        lp_w, lp_b, latent, LB, rms_p, lp_gamma, lath_p, LB, nullptr, nullptr, SL);
    // k, v projections
    gemm_k<false, false, false><<<dim3(SL / 64, 2, 8), 256>>>(
        k_w, k_b, lath_p, LB, nullptr, nullptr, kbuf_p, LB, nullptr, nullptr, SL);
    gemm_k<false, false, false><<<dim3(SL / 64, 2, 8), 256>>>(
        v_w, v_b, lath_p, LB, nullptr, nullptr, vbuf_p, LB, nullptr, nullptr, SL);

    // side path: rmsnorm -> swiglu -> query_h
    rms_k<<<(8 * SS) / 256, 256>>>(side, rms_p, SS);
    gemm_k<true, false, false><<<dim3(SS / 64, 4, 8), 256>>>(
        qmlp_in_w, qmlp_in_b, side, SB, rms_p, qn_gamma, A_p, AB, nullptr, nullptr, SS);
    glu_k<<<(int)(8L * 128 * SS / 256), 256>>>(A_p, SS);
    gemm_k<false, false, false><<<dim3(SS / 64, 2, 8), 256>>>(
        qmlp_out_w, qmlp_out_b, A_p, AB, nullptr, nullptr, qh_p, SB, nullptr, nullptr, SS);
    // q projection
    gemm_k<false, false, false><<<dim3(SS / 64, 2, 8), 256>>>(
        q_w, q_b, qh_p, SB, nullptr, nullptr, q_p, SB, nullptr, nullptr, SS);

    // fused attention (attended written over q_p)
    cudaFuncSetAttribute(attn_k, cudaFuncAttributeMaxDynamicSharedMemorySize, 119552);
    attn_k<<<dim3(128, 8), 256, 119552>>>(q_p, kbuf_p, vbuf_p, basis,
                                          score_scale, prior_scale);

    // o projection + query skip -> hidden (in d_out)
    gemm_k<false, false, true><<<dim3(SS / 64, 2, 8), 256>>>(
        o_w, o_b, q_p, SB, nullptr, nullptr, out, SB, qh_p, query_skip_scale, SS);

    // ffn: rmsnorm(hidden) -> swiglu -> residual add into hidden
    rms_k<<<(8 * SS) / 256, 256>>>(out, rms_p, SS);
    gemm_k<true, false, false><<<dim3(SS / 64, 4, 8), 256>>>(
        ffn_in_w, ffn_in_b, out, SB, rms_p, ffn_gamma, A_p, AB, nullptr, nullptr, SS);
    glu_k<<<(int)(8L * 128 * SS / 256), 256>>>(A_p, SS);
    gemm_k<false, false, true><<<dim3(SS / 64, 2, 8), 256>>>(
        ffn_out_w, ffn_out_b, A_p, AB, nullptr, nullptr, out, SB, out, nullptr, SS);
}

// round 10
// speedup vs baseline: 1.2538x; 1.2538x over previous
#include <cuda_runtime.h>
#include <cuda_bf16.h>
#include <cstdint>
#include <math.h>

// Problem constants: B=8, C=128, T=128, F=512, K=64
static constexpr int SL = 128 * 64;    // 8192  latent positions/batch
static constexpr int SS = 128 * 512;   // 65536 side positions/batch

// ---------------- scratch (device globals; no cudaMalloc allowed) ----------
__device__ float g_lat_h[8 * 128 * 8192];
__device__ float g_kbuf[8 * 128 * 8192];
__device__ float g_vbuf[8 * 128 * 8192];
__device__ float g_qh[(size_t)8 * 128 * 65536];
__device__ float g_q[(size_t)8 * 128 * 65536];      // q -> attended (in place)
__device__ float g_A[(size_t)8 * 256 * 65536];      // raw swiglu hidden (a|g planes)
// weight fragments (A-operand layout for mma.m16n8k16), hi/lo bf16 split
// total tiles: lp64 + qmlp_in128 + qmlp_out64 + q64 + k64 + v64 + o64 + ffn_in128 + ffn_out64 = 704
__device__ uint4 g_WpH[704 * 32];
__device__ uint4 g_WpL[704 * 32];

// =================== helpers ===================
__device__ __forceinline__ uint32_t smem_u32(const void* p) {
    uint32_t a;
    asm("{ .reg .u64 t; cvta.to.shared.u64 t, %1; cvt.u32.u64 %0, t; }"
        : "=r"(a) : "l"(p));
    return a;
}

// fp32 pair -> (hi,lo) bf16x2 words
__device__ __forceinline__ void split2(float v0, float v1, unsigned& hi, unsigned& lo)
{
    __nv_bfloat16 h0 = __float2bfloat16(v0);
    __nv_bfloat16 h1 = __float2bfloat16(v1);
    float r0 = v0 - __bfloat162float(h0);
    float r1 = v1 - __bfloat162float(h1);
    __nv_bfloat16 l0 = __float2bfloat16(r0);
    __nv_bfloat16 l1 = __float2bfloat16(r1);
    hi = ((unsigned)__bfloat16_as_ushort(h1) << 16) | __bfloat16_as_ushort(h0);
    lo = ((unsigned)__bfloat16_as_ushort(l1) << 16) | __bfloat16_as_ushort(l0);
}

#define MMA_BF16(dd, aa, bb)                                                   \
    asm volatile("mma.sync.aligned.m16n8k16.row.col.f32.bf16.bf16.f32 "        \
        "{%0,%1,%2,%3}, {%4,%5,%6,%7}, {%8,%9}, {%0,%1,%2,%3};"                \
        : "+f"((dd)[0]), "+f"((dd)[1]), "+f"((dd)[2]), "+f"((dd)[3])           \
        : "r"((aa).x), "r"((aa).y), "r"((aa).z), "r"((aa).w),                  \
          "r"((bb)[0]), "r"((bb)[1]))

// ---------------- weight prep: W[o][c] fp32 -> mma A-frag layout -----------
// One warp per (mt, ks) tile. Lane l regs:
//   a0=(row l>>2, c,c+1) a1=(row+8) a2=(row, c+8,c+9) a3=(row+8, c+8,c+9)
__global__ void __launch_bounds__(32) prep_w(const float* __restrict__ W,
                                             uint4* __restrict__ dh,
                                             uint4* __restrict__ dl)
{
    const int tile = blockIdx.x;           // mt*8 + ks
    const int mt = tile >> 3, ks = tile & 7;
    const int l = threadIdx.x;
    const int o = mt * 16 + (l >> 2);
    const int c = ks * 16 + (l & 3) * 2;
    const float* w0 = W + o * 128 + c;
    const float* w1 = W + (o + 8) * 128 + c;
    uint4 H, L;
    split2(w0[0], w0[1], H.x, L.x);
    split2(w1[0], w1[1], H.y, L.y);
    split2(w0[8], w0[9], H.z, L.z);
    split2(w1[8], w1[9], H.w, L.w);
    dh[tile * 32 + l] = H;
    dl[tile * 32 + l] = L;
}

// =================== bf16-split mma.sync GEMM ==============================
// Y[b, o, m] = epi( sum_c W[o,c] * Xeff[b,c,m] + bias[o] )
// CTA tile: 128 o x 64 m, K = 128.  grid = (S/64, NOUT/128, 8).
// NORM : Xeff = X * inv_rms[m] * gamma[c]
// GLUIN: Xeff = X[c] * silu(X[c+128])   (X has 256 channels)
// SILU : epilogue silu;  ADD: y += scale * add
template<bool NORM, bool GLUIN, bool SILU, bool ADD>
__global__ void __launch_bounds__(256) gemm_mm(
    const uint4* __restrict__ WpH, const uint4* __restrict__ WpL,
    const float* __restrict__ bias,
    const float* __restrict__ X, long xB,
    const float* __restrict__ gamma,
    float* __restrict__ Y, long yB,
    const float* __restrict__ addp, const float* __restrict__ addScaleP,
    int S)
{
    __shared__ unsigned char xh[16384];    // bf16 hi [k=128][n=64], XOR-swizzled
    __shared__ unsigned char xl[16384];    // bf16 lo
    __shared__ float red[256];
    __shared__ float rmss[64];

    const int tid = threadIdx.x;
    const int b = blockIdx.z;
    const int m0 = blockIdx.x * 64;
    const float* Xb = X + (long)b * xB;

    if (NORM) {
        int p = tid & 63, qd = tid >> 6;                 // 4 threads / position
        const float* xp = Xb + m0 + p;
        float s = 0.f;
        for (int c = qd; c < 128; c += 4) { float v = xp[(long)c * S]; s = fmaf(v, v, s); }
        red[tid] = s;
        __syncthreads();
        if (tid < 64)
            rmss[tid] = rsqrtf((red[tid] + red[tid + 64] + red[tid + 128] + red[tid + 192])
                               * (1.f / 128.f) + 1e-6f);
        __syncthreads();
    }

    // convert X tile -> smem bf16 hi/lo
    for (int u = tid; u < 4096; u += 256) {
        int k = u >> 5, j = u & 31;                      // j = float2 index along m
        float2 v;
        if (GLUIN) {
            float2 a = *(const float2*)(Xb + (long)k * S + m0 + 2 * j);
            float2 g = *(const float2*)(Xb + (long)(k + 128) * S + m0 + 2 * j);
            v.x = a.x * g.x / (1.f + expf(-g.x));
            v.y = a.y * g.y / (1.f + expf(-g.y));
        } else {
            v = *(const float2*)(Xb + (long)k * S + m0 + 2 * j);
            if (NORM) {
                float gm = __ldg(gamma + k);
                v.x *= rmss[2 * j] * gm;
                v.y *= rmss[2 * j + 1] * gm;
            }
        }
        unsigned hi, lo; split2(v.x, v.y, hi, lo);
        unsigned off = (unsigned)(k * 128)
                     + (((unsigned)(j * 4)) ^ (((unsigned)k & 7u) << 4));
        *(unsigned*)(xh + off) = hi;
        *(unsigned*)(xl + off) = lo;
    }
    __syncthreads();

    const int w = tid >> 5, l = tid & 31;
    const int wm = w & 3, wn = w >> 2;                   // 4(M) x 2(N) warp grid

    // ldmatrix.x4.trans lane address components:
    //   m0:(k r,   n+0)  m1:(k 8+r, n+0)  m2:(k r, n+8)  m3:(k 8+r, n+8)
    const int mi = l >> 3, r = l & 7;
    const int k_off = (mi & 1) * 8 + r;
    const int n_off = (mi >> 1) * 8;
    const unsigned mask = ((unsigned)k_off & 7u) << 4;
    const unsigned rowb = (unsigned)k_off * 128u;
    const unsigned nA = ((unsigned)((wn * 32 + n_off) * 2)) ^ mask;
    const unsigned nB = ((unsigned)((wn * 32 + 16 + n_off) * 2)) ^ mask;
    const uint32_t xh0 = smem_u32(xh) + rowb;
    const uint32_t xl0 = smem_u32(xl) + rowb;

    float d[2][4][4];
#pragma unroll
    for (int i = 0; i < 2; i++)
#pragma unroll
        for (int j = 0; j < 4; j++)
#pragma unroll
            for (int e = 0; e < 4; e++) d[i][j][e] = 0.f;

    const uint4* wph = WpH + (long)blockIdx.y * 2048;    // +8 mtiles per y
    const uint4* wpl = WpL + (long)blockIdx.y * 2048;

#pragma unroll
    for (int ks = 0; ks < 8; ks++) {
        uint4 Ah[2], Al[2];
#pragma unroll
        for (int i = 0; i < 2; i++) {
            int idx = (((wm * 2 + i) * 8) + ks) * 32 + l;
            Ah[i] = wph[idx];
            Al[i] = wpl[idx];
        }
        unsigned bh[4][2], bl[4][2];
#pragma unroll
        for (int jp = 0; jp < 2; jp++) {
            unsigned nsw = jp ? nB : nA;
            unsigned r0, r1, r2, r3;
            asm volatile("ldmatrix.sync.aligned.m8n8.x4.trans.shared.b16 "
                         "{%0,%1,%2,%3}, [%4];"
                : "=r"(r0), "=r"(r1), "=r"(r2), "=r"(r3)
                : "r"(xh0 + ks * 2048u + nsw));
            bh[2*jp][0] = r0; bh[2*jp][1] = r1; bh[2*jp+1][0] = r2; bh[2*jp+1][1] = r3;
            asm volatile("ldmatrix.sync.aligned.m8n8.x4.trans.shared.b16 "
                         "{%0,%1,%2,%3}, [%4];"
                : "=r"(r0), "=r"(r1), "=r"(r2), "=r"(r3)
                : "r"(xl0 + ks * 2048u + nsw));
            bl[2*jp][0] = r0; bl[2*jp][1] = r1; bl[2*jp+1][0] = r2; bl[2*jp+1][1] = r3;
        }
#pragma unroll
        for (int i = 0; i < 2; i++)
#pragma unroll
            for (int j = 0; j < 4; j++) {
                MMA_BF16(d[i][j], Ah[i], bh[j]);
                MMA_BF16(d[i][j], Ah[i], bl[j]);
                MMA_BF16(d[i][j], Al[i], bh[j]);
            }
    }

    // ---- epilogue: d[i][j] -> rows o0, o0+8; cols m pairs ------------------
    float scl = 1.f;
    if (ADD) { if (addScaleP) scl = __ldg(addScaleP); }
    float* Yb = Y + (long)b * yB;
    const float* Ab = ADD ? (addp + (long)b * yB) : nullptr;

#pragma unroll
    for (int i = 0; i < 2; i++) {
        int o0 = blockIdx.y * 128 + wm * 32 + i * 16 + (l >> 2);
        float b0v = __ldg(bias + o0);
        float b1v = __ldg(bias + o0 + 8);
#pragma unroll
        for (int j = 0; j < 4; j++) {
            int m = m0 + wn * 32 + j * 8 + (l & 3) * 2;
            long p0 = (long)o0 * S + m;
            long p1 = (long)(o0 + 8) * S + m;
            float y0 = d[i][j][0] + b0v, y1 = d[i][j][1] + b0v;
            float y2 = d[i][j][2] + b1v, y3 = d[i][j][3] + b1v;
            if (SILU) {
                y0 = y0 / (1.f + expf(-y0)); y1 = y1 / (1.f + expf(-y1));
                y2 = y2 / (1.f + expf(-y2)); y3 = y3 / (1.f + expf(-y3));
            }
            if (ADD) {
                float2 a0 = *(const float2*)(Ab + p0);
                float2 a1 = *(const float2*)(Ab + p1);
                y0 += scl * a0.x; y1 += scl * a0.y;
                y2 += scl * a1.x; y3 += scl * a1.y;
            }
            *(float2*)(Yb + p0) = make_float2(y0, y1);
            *(float2*)(Yb + p1) = make_float2(y2, y3);
        }
    }
}

// ---------------- fused per-(b,t) cross attention (fp32 SIMT) ---------------
__global__ void __launch_bounds__(256) attn_k(
    float* __restrict__ Q, const float* __restrict__ Kb, const float* __restrict__ Vb,
    const float* __restrict__ basis,
    const float* __restrict__ sscaleP, const float* __restrict__ pscaleP)
{
    extern __shared__ float sm[];
    float* Ks = sm;                  // [128][68]
    float* Qs = Ks + 128 * 68;       // [128][68]
    float* Vs = Qs + 128 * 68;       // [128][65]
    float* Ss = Vs + 128 * 65;       // [64][65]
    const int t = blockIdx.x, b = blockIdx.y;
    const int tid = threadIdx.x;
    const float sscale = __ldg(sscaleP), pscale = __ldg(pscaleP);

    for (int lin = tid; lin < 128 * 64; lin += 256) {
        int c = lin >> 6, kk = lin & 63;
        long g = ((long)(b * 128 + c) * 128 + t) * 64 + kk;
        Ks[c * 68 + kk] = Kb[g];
        Vs[c * 65 + kk] = Vb[g];
    }
    __syncthreads();

    const int ty = tid >> 4, tx = tid & 15;
    const int ay = tid >> 4, ax = tid & 15;

    for (int f0 = 0; f0 < 512; f0 += 64) {
        for (int lin = tid; lin < 128 * 64; lin += 256) {
            int c = lin >> 6, j = lin & 63;
            Qs[c * 68 + j] = Q[((long)(b * 128 + c) * 128 + t) * 512 + f0 + j];
        }
        __syncthreads();

        float acc[4][4] = {};
#pragma unroll 4
        for (int c = 0; c < 128; c++) {
            float4 af = *(const float4*)&Qs[c * 68 + ty * 4];
            float4 bf = *(const float4*)&Ks[c * 68 + tx * 4];
            float av[4] = {af.x, af.y, af.z, af.w};
            float bv[4] = {bf.x, bf.y, bf.z, bf.w};
#pragma unroll
            for (int i = 0; i < 4; i++)
#pragma unroll
                for (int j = 0; j < 4; j++)
                    acc[i][j] = fmaf(av[i], bv[j], acc[i][j]);
        }
#pragma unroll
        for (int i = 0; i < 4; i++)
#pragma unroll
            for (int j = 0; j < 4; j++) {
                int fl = ty * 4 + i, kk = tx * 4 + j;
                Ss[fl * 65 + kk] = acc[i][j] * sscale
                                 + pscale * basis[kk * 512 + f0 + fl];
            }
        __syncthreads();

        {
            int row = tid >> 2, q = tid & 3;
            float* rr = &Ss[row * 65];
            float mx = -3.4e38f;
            for (int i = q; i < 64; i += 4) mx = fmaxf(mx, rr[i]);
            mx = fmaxf(mx, __shfl_xor_sync(0xffffffffu, mx, 1));
            mx = fmaxf(mx, __shfl_xor_sync(0xffffffffu, mx, 2));
            float sum = 0.f;
            for (int i = q; i < 64; i += 4) { float e = expf(rr[i] - mx); rr[i] = e; sum += e; }
            sum += __shfl_xor_sync(0xffffffffu, sum, 1);
            sum += __shfl_xor_sync(0xffffffffu, sum, 2);
            float inv = 1.f / sum;
            for (int i = q; i < 64; i += 4) rr[i] *= inv;
        }
        __syncthreads();

        float at[8][4] = {};
        for (int kk = 0; kk < 64; kk++) {
            float bv[4];
#pragma unroll
            for (int j = 0; j < 4; j++) bv[j] = Ss[(ax * 4 + j) * 65 + kk];
#pragma unroll
            for (int i = 0; i < 8; i++) {
                float av = Vs[(ay * 8 + i) * 65 + kk];
#pragma unroll
                for (int j = 0; j < 4; j++) at[i][j] = fmaf(av, bv[j], at[i][j]);
            }
        }
#pragma unroll
        for (int i = 0; i < 8; i++) {
            int c = ay * 8 + i;
            float4 o4 = {at[i][0], at[i][1], at[i][2], at[i][3]};
            *(float4*)&Q[((long)(b * 128 + c) * 128 + t) * 512 + f0 + ax * 4] = o4;
        }
    }
}

// ---------------- launch ----------------------------------------------------
extern "C" void kernel_launch(void* const* d_in, const int* in_sizes, int n_in,
                              void* d_out, int out_size)
{
    const float* latent     = (const float*)d_in[0];
    const float* side       = (const float*)d_in[1];
    const float* basis      = (const float*)d_in[2];
    const float* lp_gamma   = (const float*)d_in[3];
    const float* lp_w       = (const float*)d_in[4];
    const float* lp_b       = (const float*)d_in[5];
    const float* qn_gamma   = (const float*)d_in[6];
    const float* qmlp_in_w  = (const float*)d_in[7];
    const float* qmlp_in_b  = (const float*)d_in[8];
    const float* qmlp_out_w = (const float*)d_in[9];
    const float* qmlp_out_b = (const float*)d_in[10];
    const float* q_w        = (const float*)d_in[11];
    const float* q_b        = (const float*)d_in[12];
    const float* k_w        = (const float*)d_in[13];
    const float* k_b        = (const float*)d_in[14];
    const float* v_w        = (const float*)d_in[15];
    const float* v_b        = (const float*)d_in[16];
    const float* o_w        = (const float*)d_in[17];
    const float* o_b        = (const float*)d_in[18];
    const float* ffn_gamma  = (const float*)d_in[19];
    const float* ffn_in_w   = (const float*)d_in[20];
    const float* ffn_in_b   = (const float*)d_in[21];
    const float* ffn_out_w  = (const float*)d_in[22];
    const float* ffn_out_b  = (const float*)d_in[23];
    const float* score_scale      = (const float*)d_in[24];
    const float* prior_scale      = (const float*)d_in[25];
    const float* query_skip_scale = (const float*)d_in[26];
    float* out = (float*)d_out;

    float *lath_p, *kbuf_p, *vbuf_p, *qh_p, *q_p, *A_p;
    uint4 *wh, *wl;
    cudaGetSymbolAddress((void**)&lath_p, g_lat_h);
    cudaGetSymbolAddress((void**)&kbuf_p, g_kbuf);
    cudaGetSymbolAddress((void**)&vbuf_p, g_vbuf);
    cudaGetSymbolAddress((void**)&qh_p,   g_qh);
    cudaGetSymbolAddress((void**)&q_p,    g_q);
    cudaGetSymbolAddress((void**)&A_p,    g_A);
    cudaGetSymbolAddress((void**)&wh,     g_WpH);
    cudaGetSymbolAddress((void**)&wl,     g_WpL);

    // fragment-buffer tile offsets (x32 uint4 per tile)
    const int OFF_LP = 0, OFF_QIN = 64, OFF_QOUT = 192, OFF_Q = 256,
              OFF_K = 320, OFF_V = 384, OFF_O = 448, OFF_FIN = 512, OFF_FOUT = 640;

    // weight prep (all 9 matrices)
    prep_w<<<64,  32>>>(lp_w,       wh + OFF_LP   * 32, wl + OFF_LP   * 32);
    prep_w<<<128, 32>>>(qmlp_in_w,  wh + OFF_QIN  * 32, wl + OFF_QIN  * 32);
    prep_w<<<64,  32>>>(qmlp_out_w, wh + OFF_QOUT * 32, wl + OFF_QOUT * 32);
    prep_w<<<64,  32>>>(q_w,        wh + OFF_Q    * 32, wl + OFF_Q    * 32);
    prep_w<<<64,  32>>>(k_w,        wh + OFF_K    * 32, wl + OFF_K    * 32);
    prep_w<<<64,  32>>>(v_w,        wh + OFF_V    * 32, wl + OFF_V    * 32);
    prep_w<<<64,  32>>>(o_w,        wh + OFF_O    * 32, wl + OFF_O    * 32);
    prep_w<<<128, 32>>>(ffn_in_w,   wh + OFF_FIN  * 32, wl + OFF_FIN  * 32);
    prep_w<<<64,  32>>>(ffn_out_w,  wh + OFF_FOUT * 32, wl + OFF_FOUT * 32);

    const long LB = 128L * SL;       // latent batch stride (128 ch)
    const long SB = 128L * SS;       // side batch stride (128 ch)
    const long AB = 256L * SS;       // swiglu hidden batch stride (256 ch)

    dim3 gl(SL / 64, 1, 8), gs(SS / 64, 1, 8), gs2(SS / 64, 2, 8);

    // latent path: rmsnorm -> lp conv -> silu (fused)
    gemm_mm<true, false, true, false><<<gl, 256>>>(
        wh + OFF_LP * 32, wl + OFF_LP * 32, lp_b, latent, LB, lp_gamma,
        lath_p, LB, nullptr, nullptr, SL);
    gemm_mm<false, false, false, false><<<gl, 256>>>(
        wh + OFF_K * 32, wl + OFF_K * 32, k_b, lath_p, LB, nullptr,
        kbuf_p, LB, nullptr, nullptr, SL);
    gemm_mm<false, false, false, false><<<gl, 256>>>(
        wh + OFF_V * 32, wl + OFF_V * 32, v_b, lath_p, LB, nullptr,
        vbuf_p, LB, nullptr, nullptr, SL);

    // side path: rmsnorm -> qmlp_in (raw a|g) -> [GLU in consumer] -> qmlp_out -> q
    gemm_mm<true, false, false, false><<<gs2, 256>>>(
        wh + OFF_QIN * 32, wl + OFF_QIN * 32, qmlp_in_b, side, SB, qn_gamma,
        A_p, AB, nullptr, nullptr, SS);
    gemm_mm<false, true, false, false><<<gs, 256>>>(
        wh + OFF_QOUT * 32, wl + OFF_QOUT * 32, qmlp_out_b, A_p, AB, nullptr,
        qh_p, SB, nullptr, nullptr, SS);
    gemm_mm<false, false, false, false><<<gs, 256>>>(
        wh + OFF_Q * 32, wl + OFF_Q * 32, q_b, qh_p, SB, nullptr,
        q_p, SB, nullptr, nullptr, SS);

    // fused attention (attended written over q_p)
    cudaFuncSetAttribute(attn_k, cudaFuncAttributeMaxDynamicSharedMemorySize, 119552);
    attn_k<<<dim3(128, 8), 256, 119552>>>(q_p, kbuf_p, vbuf_p, basis,
                                          score_scale, prior_scale);

    // o projection + query skip -> hidden (d_out)
    gemm_mm<false, false, false, true><<<gs, 256>>>(
        wh + OFF_O * 32, wl + OFF_O * 32, o_b, q_p, SB, nullptr,
        out, SB, qh_p, query_skip_scale, SS);

    // ffn: rmsnorm -> ffn_in (raw a|g) -> [GLU in consumer] -> ffn_out + residual
    gemm_mm<true, false, false, false><<<gs2, 256>>>(
        wh + OFF_FIN * 32, wl + OFF_FIN * 32, ffn_in_b, out, SB, ffn_gamma,
        A_p, AB, nullptr, nullptr, SS);
    gemm_mm<false, true, false, true><<<gs, 256>>>(
        wh + OFF_FOUT * 32, wl + OFF_FOUT * 32, ffn_out_b, A_p, AB, nullptr,
        out, SB, out, nullptr, SS);
}

// round 11
// speedup vs baseline: 1.8173x; 1.4495x over previous
#include <cuda_runtime.h>
#include <cuda_fp16.h>
#include <cstdint>
#include <math.h>

// Problem constants: B=8, C=128, T=128, F=512, K=64
static constexpr int SL = 128 * 64;    // 8192  latent positions/batch
static constexpr int SS = 128 * 512;   // 65536 side positions/batch

// ---------------- scratch (device globals; no cudaMalloc allowed) ----------
__device__ float g_lat_h[8 * 128 * 8192];
__device__ float g_kbuf[8 * 128 * 8192];
__device__ float g_vbuf[8 * 128 * 8192];
__device__ float g_qh[(size_t)8 * 128 * 65536];
__device__ float g_q[(size_t)8 * 128 * 65536];      // q -> attended (in place)
__device__ float g_A[(size_t)8 * 256 * 65536];      // raw swiglu hidden (a|g planes)
// fp16 weight fragments (A-operand layout for mma.m16n8k16)
// tiles: lp64 qmlp_in128 qmlp_out64 q64 k64 v64 o64 ffn_in128 ffn_out64 = 704
__device__ uint4 g_Wp[704 * 32];

// =================== helpers ===================
__device__ __forceinline__ uint32_t smem_u32(const void* p) {
    uint32_t a;
    asm("{ .reg .u64 t; cvta.to.shared.u64 t, %1; cvt.u32.u64 %0, t; }"
        : "=r"(a) : "l"(p));
    return a;
}
__device__ __forceinline__ unsigned pack_h2(float a, float b) {
    __half2 h = __floats2half2_rn(a, b);
    return *(unsigned*)&h;
}

#define MMA_F16(dd, aa, bb)                                                    \
    asm volatile("mma.sync.aligned.m16n8k16.row.col.f32.f16.f16.f32 "          \
        "{%0,%1,%2,%3}, {%4,%5,%6,%7}, {%8,%9}, {%0,%1,%2,%3};"                \
        : "+f"((dd)[0]), "+f"((dd)[1]), "+f"((dd)[2]), "+f"((dd)[3])           \
        : "r"((aa).x), "r"((aa).y), "r"((aa).z), "r"((aa).w),                  \
          "r"((bb)[0]), "r"((bb)[1]))

// ---------------- single weight-prep kernel (all 9 matrices) ---------------
// One warp per 16(o)x16(c) tile; lane l holds the mma A-frag regs:
//   a0=(row l>>2, c,c+1) a1=(row+8, c,c+1) a2=(row, c+8,c+9) a3=(row+8, c+8,c+9)
struct WPtrs { const float* p[9]; };
__constant__ int c_tile_start[10] = {0, 64, 192, 256, 320, 384, 448, 512, 640, 704};

__global__ void __launch_bounds__(256) prep_all(WPtrs wp, uint4* __restrict__ dst)
{
    int gw = (blockIdx.x * 256 + threadIdx.x) >> 5;     // global tile index
    if (gw >= 704) return;
    int mi = 0;
    while (gw >= c_tile_start[mi + 1]) mi++;
    int tile = gw - c_tile_start[mi];
    const float* W = wp.p[mi];
    const int mt = tile >> 3, ks = tile & 7;
    const int l = threadIdx.x & 31;
    const int o = mt * 16 + (l >> 2);
    const int c = ks * 16 + (l & 3) * 2;
    const float* w0 = W + o * 128 + c;
    const float* w1 = W + (o + 8) * 128 + c;
    uint4 H;
    H.x = pack_h2(w0[0], w0[1]);
    H.y = pack_h2(w1[0], w1[1]);
    H.z = pack_h2(w0[8], w0[9]);
    H.w = pack_h2(w1[8], w1[9]);
    dst[gw * 32 + l] = H;
}

// =================== fp16 mma.sync GEMM ====================================
// Y[b, o, m] = epi( sum_c W[o,c] * Xeff[b,c,m] + bias[o] )
// CTA tile: 128 o x 64 m, K = 128.  grid = (S/64, NOUT/128, 8).
// NORM : Xeff = X * inv_rms[m] * gamma[c]
// GLUIN: Xeff = X[c] * silu(X[c+128])   (X has 256 channels)
// SILU : epilogue silu;  ADD: y += scale * add
template<bool NORM, bool GLUIN, bool SILU, bool ADD>
__global__ void __launch_bounds__(256) gemm_mm(
    const uint4* __restrict__ Wp,
    const float* __restrict__ bias,
    const float* __restrict__ X, long xB,
    const float* __restrict__ gamma,
    float* __restrict__ Y, long yB,
    const float* __restrict__ addp, const float* __restrict__ addScaleP,
    int S)
{
    __shared__ unsigned char xh[16384];    // fp16 [k=128][n=64], XOR-swizzled
    __shared__ float red[256];
    __shared__ float rmss[64];

    const int tid = threadIdx.x;
    const int b = blockIdx.z;
    const int m0 = blockIdx.x * 64;
    const float* Xb = X + (long)b * xB;

    if (NORM) {
        int p = tid & 63, qd = tid >> 6;                 // 4 threads / position
        const float* xp = Xb + m0 + p;
        float s = 0.f;
        for (int c = qd; c < 128; c += 4) { float v = xp[(long)c * S]; s = fmaf(v, v, s); }
        red[tid] = s;
        __syncthreads();
        if (tid < 64)
            rmss[tid] = rsqrtf((red[tid] + red[tid + 64] + red[tid + 128] + red[tid + 192])
                               * (1.f / 128.f) + 1e-6f);
        __syncthreads();
    }

    // convert X tile -> smem fp16
    for (int u = tid; u < 4096; u += 256) {
        int k = u >> 5, j = u & 31;                      // j = float2 index along m
        float2 v;
        if (GLUIN) {
            float2 a = *(const float2*)(Xb + (long)k * S + m0 + 2 * j);
            float2 g = *(const float2*)(Xb + (long)(k + 128) * S + m0 + 2 * j);
            v.x = a.x * g.x / (1.f + expf(-g.x));
            v.y = a.y * g.y / (1.f + expf(-g.y));
        } else {
            v = *(const float2*)(Xb + (long)k * S + m0 + 2 * j);
            if (NORM) {
                float gm = __ldg(gamma + k);
                v.x *= rmss[2 * j] * gm;
                v.y *= rmss[2 * j + 1] * gm;
            }
        }
        unsigned off = (unsigned)(k * 128)
                     + (((unsigned)(j * 4)) ^ (((unsigned)k & 7u) << 4));
        *(unsigned*)(xh + off) = pack_h2(v.x, v.y);
    }
    __syncthreads();

    const int w = tid >> 5, l = tid & 31;
    const int wm = w & 3, wn = w >> 2;                   // 4(M) x 2(N) warp grid

    // ldmatrix.x4.trans lane address components
    const int mi = l >> 3, r = l & 7;
    const int k_off = (mi & 1) * 8 + r;
    const int n_off = (mi >> 1) * 8;
    const unsigned mask = ((unsigned)k_off & 7u) << 4;
    const unsigned rowb = (unsigned)k_off * 128u;
    const unsigned nA = ((unsigned)((wn * 32 + n_off) * 2)) ^ mask;
    const unsigned nB = ((unsigned)((wn * 32 + 16 + n_off) * 2)) ^ mask;
    const uint32_t xh0 = smem_u32(xh) + rowb;

    float d[2][4][4];
#pragma unroll
    for (int i = 0; i < 2; i++)
#pragma unroll
        for (int j = 0; j < 4; j++)
#pragma unroll
            for (int e = 0; e < 4; e++) d[i][j][e] = 0.f;

    const uint4* wpt = Wp + (long)blockIdx.y * 2048;     // +8 mtiles per y

#pragma unroll
    for (int ks = 0; ks < 8; ks++) {
        uint4 Ah[2];
#pragma unroll
        for (int i = 0; i < 2; i++)
            Ah[i] = wpt[(((wm * 2 + i) * 8) + ks) * 32 + l];
        unsigned bh[4][2];
#pragma unroll
        for (int jp = 0; jp < 2; jp++) {
            unsigned nsw = jp ? nB : nA;
            unsigned r0, r1, r2, r3;
            asm volatile("ldmatrix.sync.aligned.m8n8.x4.trans.shared.b16 "
                         "{%0,%1,%2,%3}, [%4];"
                : "=r"(r0), "=r"(r1), "=r"(r2), "=r"(r3)
                : "r"(xh0 + ks * 2048u + nsw));
            bh[2*jp][0] = r0; bh[2*jp][1] = r1; bh[2*jp+1][0] = r2; bh[2*jp+1][1] = r3;
        }
#pragma unroll
        for (int i = 0; i < 2; i++)
#pragma unroll
            for (int j = 0; j < 4; j++)
                MMA_F16(d[i][j], Ah[i], bh[j]);
    }

    // ---- epilogue ----------------------------------------------------------
    float scl = 1.f;
    if (ADD) { if (addScaleP) scl = __ldg(addScaleP); }
    float* Yb = Y + (long)b * yB;
    const float* Ab = ADD ? (addp + (long)b * yB) : nullptr;

#pragma unroll
    for (int i = 0; i < 2; i++) {
        int o0 = blockIdx.y * 128 + wm * 32 + i * 16 + (l >> 2);
        float b0v = __ldg(bias + o0);
        float b1v = __ldg(bias + o0 + 8);
#pragma unroll
        for (int j = 0; j < 4; j++) {
            int m = m0 + wn * 32 + j * 8 + (l & 3) * 2;
            long p0 = (long)o0 * S + m;
            long p1 = (long)(o0 + 8) * S + m;
            float y0 = d[i][j][0] + b0v, y1 = d[i][j][1] + b0v;
            float y2 = d[i][j][2] + b1v, y3 = d[i][j][3] + b1v;
            if (SILU) {
                y0 = y0 / (1.f + expf(-y0)); y1 = y1 / (1.f + expf(-y1));
                y2 = y2 / (1.f + expf(-y2)); y3 = y3 / (1.f + expf(-y3));
            }
            if (ADD) {
                float2 a0 = *(const float2*)(Ab + p0);
                float2 a1 = *(const float2*)(Ab + p1);
                y0 += scl * a0.x; y1 += scl * a0.y;
                y2 += scl * a1.x; y3 += scl * a1.y;
            }
            *(float2*)(Yb + p0) = make_float2(y0, y1);
            *(float2*)(Yb + p1) = make_float2(y2, y3);
        }
    }
}

// ---------------- fused per-(b,t) cross attention (fp32 SIMT) ---------------
__global__ void __launch_bounds__(256) attn_k(
    float* __restrict__ Q, const float* __restrict__ Kb, const float* __restrict__ Vb,
    const float* __restrict__ basis,
    const float* __restrict__ sscaleP, const float* __restrict__ pscaleP)
{
    extern __shared__ float sm[];
    float* Ks = sm;                  // [128][68]
    float* Qs = Ks + 128 * 68;       // [128][68]
    float* Vs = Qs + 128 * 68;       // [128][65]
    float* Ss = Vs + 128 * 65;       // [64][65]
    const int t = blockIdx.x, b = blockIdx.y;
    const int tid = threadIdx.x;
    const float sscale = __ldg(sscaleP), pscale = __ldg(pscaleP);

    for (int lin = tid; lin < 128 * 64; lin += 256) {
        int c = lin >> 6, kk = lin & 63;
        long g = ((long)(b * 128 + c) * 128 + t) * 64 + kk;
        Ks[c * 68 + kk] = Kb[g];
        Vs[c * 65 + kk] = Vb[g];
    }
    __syncthreads();

    const int ty = tid >> 4, tx = tid & 15;
    const int ay = tid >> 4, ax = tid & 15;

    for (int f0 = 0; f0 < 512; f0 += 64) {
        for (int lin = tid; lin < 128 * 64; lin += 256) {
            int c = lin >> 6, j = lin & 63;
            Qs[c * 68 + j] = Q[((long)(b * 128 + c) * 128 + t) * 512 + f0 + j];
        }
        __syncthreads();

        float acc[4][4] = {};
#pragma unroll 4
        for (int c = 0; c < 128; c++) {
            float4 af = *(const float4*)&Qs[c * 68 + ty * 4];
            float4 bf = *(const float4*)&Ks[c * 68 + tx * 4];
            float av[4] = {af.x, af.y, af.z, af.w};
            float bv[4] = {bf.x, bf.y, bf.z, bf.w};
#pragma unroll
            for (int i = 0; i < 4; i++)
#pragma unroll
                for (int j = 0; j < 4; j++)
                    acc[i][j] = fmaf(av[i], bv[j], acc[i][j]);
        }
#pragma unroll
        for (int i = 0; i < 4; i++)
#pragma unroll
            for (int j = 0; j < 4; j++) {
                int fl = ty * 4 + i, kk = tx * 4 + j;
                Ss[fl * 65 + kk] = acc[i][j] * sscale
                                 + pscale * basis[kk * 512 + f0 + fl];
            }
        __syncthreads();

        {
            int row = tid >> 2, q = tid & 3;
            float* rr = &Ss[row * 65];
            float mx = -3.4e38f;
            for (int i = q; i < 64; i += 4) mx = fmaxf(mx, rr[i]);
            mx = fmaxf(mx, __shfl_xor_sync(0xffffffffu, mx, 1));
            mx = fmaxf(mx, __shfl_xor_sync(0xffffffffu, mx, 2));
            float sum = 0.f;
            for (int i = q; i < 64; i += 4) { float e = expf(rr[i] - mx); rr[i] = e; sum += e; }
            sum += __shfl_xor_sync(0xffffffffu, sum, 1);
            sum += __shfl_xor_sync(0xffffffffu, sum, 2);
            float inv = 1.f / sum;
            for (int i = q; i < 64; i += 4) rr[i] *= inv;
        }
        __syncthreads();

        float at[8][4] = {};
        for (int kk = 0; kk < 64; kk++) {
            float bv[4];
#pragma unroll
            for (int j = 0; j < 4; j++) bv[j] = Ss[(ax * 4 + j) * 65 + kk];
#pragma unroll
            for (int i = 0; i < 8; i++) {
                float av = Vs[(ay * 8 + i) * 65 + kk];
#pragma unroll
                for (int j = 0; j < 4; j++) at[i][j] = fmaf(av, bv[j], at[i][j]);
            }
        }
#pragma unroll
        for (int i = 0; i < 8; i++) {
            int c = ay * 8 + i;
            float4 o4 = {at[i][0], at[i][1], at[i][2], at[i][3]};
            *(float4*)&Q[((long)(b * 128 + c) * 128 + t) * 512 + f0 + ax * 4] = o4;
        }
    }
}

// ---------------- launch ----------------------------------------------------
extern "C" void kernel_launch(void* const* d_in, const int* in_sizes, int n_in,
                              void* d_out, int out_size)
{
    const float* latent     = (const float*)d_in[0];
    const float* side       = (const float*)d_in[1];
    const float* basis      = (const float*)d_in[2];
    const float* lp_gamma   = (const float*)d_in[3];
    const float* lp_w       = (const float*)d_in[4];
    const float* lp_b       = (const float*)d_in[5];
    const float* qn_gamma   = (const float*)d_in[6];
    const float* qmlp_in_w  = (const float*)d_in[7];
    const float* qmlp_in_b  = (const float*)d_in[8];
    const float* qmlp_out_w = (const float*)d_in[9];
    const float* qmlp_out_b = (const float*)d_in[10];
    const float* q_w        = (const float*)d_in[11];
    const float* q_b        = (const float*)d_in[12];
    const float* k_w        = (const float*)d_in[13];
    const float* k_b        = (const float*)d_in[14];
    const float* v_w        = (const float*)d_in[15];
    const float* v_b        = (const float*)d_in[16];
    const float* o_w        = (const float*)d_in[17];
    const float* o_b        = (const float*)d_in[18];
    const float* ffn_gamma  = (const float*)d_in[19];
    const float* ffn_in_w   = (const float*)d_in[20];
    const float* ffn_in_b   = (const float*)d_in[21];
    const float* ffn_out_w  = (const float*)d_in[22];
    const float* ffn_out_b  = (const float*)d_in[23];
    const float* score_scale      = (const float*)d_in[24];
    const float* prior_scale      = (const float*)d_in[25];
    const float* query_skip_scale = (const float*)d_in[26];
    float* out = (float*)d_out;

    float *lath_p, *kbuf_p, *vbuf_p, *qh_p, *q_p, *A_p;
    uint4 *wfrag;
    cudaGetSymbolAddress((void**)&lath_p, g_lat_h);
    cudaGetSymbolAddress((void**)&kbuf_p, g_kbuf);
    cudaGetSymbolAddress((void**)&vbuf_p, g_vbuf);
    cudaGetSymbolAddress((void**)&qh_p,   g_qh);
    cudaGetSymbolAddress((void**)&q_p,    g_q);
    cudaGetSymbolAddress((void**)&A_p,    g_A);
    cudaGetSymbolAddress((void**)&wfrag,  g_Wp);

    // fragment-buffer tile offsets (match c_tile_start order)
    const int OFF_LP = 0, OFF_QIN = 64, OFF_QOUT = 192, OFF_Q = 256,
              OFF_K = 320, OFF_V = 384, OFF_O = 448, OFF_FIN = 512, OFF_FOUT = 640;

    // single weight-prep launch (all 9 matrices)
    WPtrs wp;
    wp.p[0] = lp_w;      wp.p[1] = qmlp_in_w; wp.p[2] = qmlp_out_w;
    wp.p[3] = q_w;       wp.p[4] = k_w;       wp.p[5] = v_w;
    wp.p[6] = o_w;       wp.p[7] = ffn_in_w;  wp.p[8] = ffn_out_w;
    prep_all<<<88, 256>>>(wp, wfrag);

    const long LB = 128L * SL;       // latent batch stride (128 ch)
    const long SB = 128L * SS;       // side batch stride (128 ch)
    const long AB = 256L * SS;       // swiglu hidden batch stride (256 ch)

    dim3 gl(SL / 64, 1, 8), gs(SS / 64, 1, 8), gs2(SS / 64, 2, 8);

    // latent path: rmsnorm -> lp conv -> silu (fused)
    gemm_mm<true, false, true, false><<<gl, 256>>>(
        wfrag + OFF_LP * 32, lp_b, latent, LB, lp_gamma,
        lath_p, LB, nullptr, nullptr, SL);
    gemm_mm<false, false, false, false><<<gl, 256>>>(
        wfrag + OFF_K * 32, k_b, lath_p, LB, nullptr,
        kbuf_p, LB, nullptr, nullptr, SL);
    gemm_mm<false, false, false, false><<<gl, 256>>>(
        wfrag + OFF_V * 32, v_b, lath_p, LB, nullptr,
        vbuf_p, LB, nullptr, nullptr, SL);

    // side path: rmsnorm -> qmlp_in (raw a|g) -> [GLU in consumer] -> qmlp_out -> q
    gemm_mm<true, false, false, false><<<gs2, 256>>>(
        wfrag + OFF_QIN * 32, qmlp_in_b, side, SB, qn_gamma,
        A_p, AB, nullptr, nullptr, SS);
    gemm_mm<false, true, false, false><<<gs, 256>>>(
        wfrag + OFF_QOUT * 32, qmlp_out_b, A_p, AB, nullptr,
        qh_p, SB, nullptr, nullptr, SS);
    gemm_mm<false, false, false, false><<<gs, 256>>>(
        wfrag + OFF_Q * 32, q_b, qh_p, SB, nullptr,
        q_p, SB, nullptr, nullptr, SS);

    // fused attention (attended written over q_p)
    cudaFuncSetAttribute(attn_k, cudaFuncAttributeMaxDynamicSharedMemorySize, 119552);
    attn_k<<<dim3(128, 8), 256, 119552>>>(q_p, kbuf_p, vbuf_p, basis,
                                          score_scale, prior_scale);

    // o projection + query skip -> hidden (d_out)
    gemm_mm<false, false, false, true><<<gs, 256>>>(
        wfrag + OFF_O * 32, o_b, q_p, SB, nullptr,
        out, SB, qh_p, query_skip_scale, SS);

    // ffn: rmsnorm -> ffn_in (raw a|g) -> [GLU in consumer] -> ffn_out + residual
    gemm_mm<true, false, false, false><<<gs2, 256>>>(
        wfrag + OFF_FIN * 32, ffn_in_b, out, SB, ffn_gamma,
        A_p, AB, nullptr, nullptr, SS);
    gemm_mm<false, true, false, true><<<gs, 256>>>(
        wfrag + OFF_FOUT * 32, ffn_out_b, A_p, AB, nullptr,
        out, SB, out, nullptr, SS);
}

// round 12
// speedup vs baseline: 2.0653x; 1.1364x over previous
#include <cuda_runtime.h>
#include <cuda_fp16.h>
#include <cstdint>
#include <math.h>

// Problem constants: B=8, C=128, T=128, F=512, K=64
static constexpr int SL = 8192;    // latent positions/batch
static constexpr int SS = 65536;   // side positions/batch

// ---------------- scratch (device globals; no cudaMalloc allowed) ----------
__device__ float g_kbuf[8 * 128 * 8192];
__device__ float g_vbuf[8 * 128 * 8192];
__device__ float g_qh[(size_t)8 * 128 * 65536];
__device__ float g_q[(size_t)8 * 128 * 65536];
// fp16 pre-swizzled tile tensors: 32KB tiles of [128 k][128 m]
__device__ uint4 g_lat16[(size_t)8 * 64 * 2048];
__device__ uint4 g_A16[(size_t)8 * 512 * 2048];      // GLU'd swiglu hidden (both MLPs)
__device__ uint4 g_qh16[(size_t)8 * 512 * 2048];
__device__ uint4 g_att16[(size_t)8 * 512 * 2048];
// fp16 weight fragments (A-operand layout for mma.m16n8k16)
__device__ uint4 g_Wp[704 * 32];

// =================== helpers ===================
__device__ __forceinline__ uint32_t smem_u32(const void* p) {
    uint32_t a;
    asm("{ .reg .u64 t; cvta.to.shared.u64 t, %1; cvt.u32.u64 %0, t; }"
        : "=r"(a) : "l"(p));
    return a;
}
__device__ __forceinline__ unsigned pack_h2(float a, float b) {
    __half2 h = __floats2half2_rn(a, b);
    return *(unsigned*)&h;
}
__device__ __forceinline__ float silu(float g) { return g / (1.f + expf(-g)); }
// byte offset inside a 32KB [128k][128m] fp16 tile (256B rows, XOR-swizzled)
__device__ __forceinline__ unsigned sw_off(int k, int mp) {
    return (unsigned)k * 256u + (((unsigned)mp * 2u) ^ (((unsigned)k & 7u) << 4));
}

#define MMA_F16(dd, aa, bb)                                                    \
    asm volatile("mma.sync.aligned.m16n8k16.row.col.f32.f16.f16.f32 "          \
        "{%0,%1,%2,%3}, {%4,%5,%6,%7}, {%8,%9}, {%0,%1,%2,%3};"                \
        : "+f"((dd)[0]), "+f"((dd)[1]), "+f"((dd)[2]), "+f"((dd)[3])           \
        : "r"((aa).x), "r"((aa).y), "r"((aa).z), "r"((aa).w),                  \
          "r"((bb)[0]), "r"((bb)[1]))

#define LDMX4T(b0, b1, b2, b3, addr)                                           \
    asm volatile("ldmatrix.sync.aligned.m8n8.x4.trans.shared.b16 "             \
        "{%0,%1,%2,%3}, [%4];"                                                 \
        : "=r"(b0), "=r"(b1), "=r"(b2), "=r"(b3) : "r"(addr))

// ---------------- single weight-prep kernel (all 9 matrices) ---------------
struct WPtrs { const float* p[9]; };
__constant__ int c_tile_start[10] = {0, 64, 192, 256, 320, 384, 448, 512, 640, 704};

__global__ void __launch_bounds__(256) prep_all(WPtrs wp, uint4* __restrict__ dst)
{
    int gw = (blockIdx.x * 256 + threadIdx.x) >> 5;     // global tile index
    if (gw >= 704) return;
    int mi = 0;
    while (gw >= c_tile_start[mi + 1]) mi++;
    int tile = gw - c_tile_start[mi];
    const float* W = wp.p[mi];
    const int mt = tile >> 3, ks = tile & 7;
    const int l = threadIdx.x & 31;
    const int o = mt * 16 + (l >> 2);
    const int c = ks * 16 + (l & 3) * 2;
    const float* w0 = W + o * 128 + c;
    const float* w1 = W + (o + 8) * 128 + c;
    uint4 H;
    H.x = pack_h2(w0[0], w0[1]);
    H.y = pack_h2(w1[0], w1[1]);
    H.z = pack_h2(w0[8], w0[9]);
    H.w = pack_h2(w1[8], w1[9]);
    dst[gw * 32 + l] = H;
}

// =================== G1: fp32+RMSNorm input GEMM -> fp16sw output ==========
// NOUT=128: lp layer, SILU epilogue -> fp16sw tile.
// NOUT=256: swiglu-in layer, GLU epilogue (a*silu(g)) -> 128-ch fp16sw tile.
template<int NOUT>
__global__ void __launch_bounds__(256, 2) gemm_f32in(
    const uint4* __restrict__ Wp, const float* __restrict__ bias,
    const float* __restrict__ X, const float* __restrict__ gamma,
    uint4* __restrict__ Y16, int S)
{
    constexpr int MT   = (NOUT == 128) ? 128 : 64;
    constexpr int ROWB = MT * 2;
    constexpr int ISUB = NOUT / 64;        // 2 or 4
    constexpr int WARP_M = MT / 2;         // 64 or 32
    constexpr int JQ  = WARP_M / 16;       // 4 or 2
    constexpr int JS  = WARP_M / 8;        // 8 or 4
    constexpr int TPP = 256 / MT;          // rms threads per position

    __shared__ __align__(16) unsigned char xh[128 * ROWB];
    __shared__ float red[256];
    __shared__ float rmss[MT];

    const int tid = threadIdx.x;
    const int b = blockIdx.z;
    const int m0 = blockIdx.x * MT;
    const float* Xb = X + (size_t)b * 128 * S;

    // ---- RMS over channel dim ----
    {
        int p = tid % MT, qd = tid / MT;
        const float* xp = Xb + m0 + p;
        float s = 0.f;
        for (int c = qd; c < 128; c += TPP) { float v = xp[(size_t)c * S]; s = fmaf(v, v, s); }
        red[tid] = s;
        __syncthreads();
        if (tid < MT) {
            float t = 0.f;
#pragma unroll
            for (int e = 0; e < TPP; e++) t += red[tid + e * MT];
            rmss[tid] = rsqrtf(t * (1.f / 128.f) + 1e-6f);
        }
        __syncthreads();
    }

    // ---- convert X tile -> smem fp16 (batched for MLP) ----
    constexpr int TOT2 = 128 * MT / 2;                 // float2 elements
    for (int base = 0; base < TOT2; base += 2048) {
        float2 vv[8];
#pragma unroll
        for (int e = 0; e < 8; e++) {
            int u = base + e * 256 + tid;
            int k = u / (MT / 2), j = u % (MT / 2);
            vv[e] = *(const float2*)(Xb + (size_t)k * S + m0 + 2 * j);
        }
#pragma unroll
        for (int e = 0; e < 8; e++) {
            int u = base + e * 256 + tid;
            int k = u / (MT / 2), j = u % (MT / 2);
            float gm = __ldg(gamma + k);
            float2 v = vv[e];
            v.x *= rmss[2 * j] * gm;
            v.y *= rmss[2 * j + 1] * gm;
            unsigned off = (unsigned)k * ROWB
                         + (((unsigned)(j * 4)) ^ (((unsigned)k & 7u) << 4));
            *(unsigned*)(xh + off) = pack_h2(v.x, v.y);
        }
    }
    __syncthreads();

    // ---- mainloop ----
    const int w = tid >> 5, l = tid & 31;
    const int wm = w & 3, wn = w >> 2;
    const int mi = l >> 3, r = l & 7;
    const int k_off = (mi & 1) * 8 + r;
    const int n_off = (mi >> 1) * 8;
    const unsigned mask = ((unsigned)k_off & 7u) << 4;
    const uint32_t xrow = smem_u32(xh) + (unsigned)k_off * ROWB;

    float d[ISUB][JS][4];
#pragma unroll
    for (int i = 0; i < ISUB; i++)
#pragma unroll
        for (int j = 0; j < JS; j++)
#pragma unroll
            for (int e = 0; e < 4; e++) d[i][j][e] = 0.f;

#pragma unroll
    for (int ks = 0; ks < 8; ks++) {
        uint4 Ah[ISUB];
#pragma unroll
        for (int i = 0; i < ISUB; i++) {
            int mt = (NOUT == 256 && i >= 2) ? (8 + wm * 2 + (i - 2)) : (wm * 2 + i);
            Ah[i] = Wp[(mt * 8 + ks) * 32 + l];
        }
        unsigned bh[JS][2];
#pragma unroll
        for (int jp = 0; jp < JQ; jp++) {
            unsigned col = (unsigned)(wn * WARP_M + jp * 16 + n_off);
            unsigned r0, r1, r2, r3;
            LDMX4T(r0, r1, r2, r3, xrow + (unsigned)ks * 16u * ROWB + ((col * 2u) ^ mask));
            bh[2 * jp][0] = r0; bh[2 * jp][1] = r1;
            bh[2 * jp + 1][0] = r2; bh[2 * jp + 1][1] = r3;
        }
#pragma unroll
        for (int i = 0; i < ISUB; i++)
#pragma unroll
            for (int j = 0; j < JS; j++)
                MMA_F16(d[i][j], Ah[i], bh[j]);
    }

    // ---- epilogue -> fp16sw tile ----
    const int MTILES = S >> 7;
    unsigned char* tb = (unsigned char*)(Y16 + (size_t)(b * MTILES + (m0 >> 7)) * 2048);
    const int mpb = m0 & 127;                          // 0 or 64
#pragma unroll
    for (int i = 0; i < 2; i++) {
        int k0 = wm * 32 + i * 16 + (l >> 2);
        if (NOUT == 128) {
            float b0 = __ldg(bias + k0), b1 = __ldg(bias + k0 + 8);
#pragma unroll
            for (int j = 0; j < JS; j++) {
                int m = mpb + wn * WARP_M + j * 8 + (l & 3) * 2;
                float y0 = silu(d[i][j][0] + b0), y1 = silu(d[i][j][1] + b0);
                float y2 = silu(d[i][j][2] + b1), y3 = silu(d[i][j][3] + b1);
                *(unsigned*)(tb + sw_off(k0, m))     = pack_h2(y0, y1);
                *(unsigned*)(tb + sw_off(k0 + 8, m)) = pack_h2(y2, y3);
            }
        } else {
            float ba0 = __ldg(bias + k0), ba1 = __ldg(bias + k0 + 8);
            float bg0 = __ldg(bias + 128 + k0), bg1 = __ldg(bias + 128 + k0 + 8);
#pragma unroll
            for (int j = 0; j < JS; j++) {
                int m = mpb + wn * WARP_M + j * 8 + (l & 3) * 2;
                float y0 = (d[i][j][0] + ba0) * silu(d[i + 2][j][0] + bg0);
                float y1 = (d[i][j][1] + ba0) * silu(d[i + 2][j][1] + bg0);
                float y2 = (d[i][j][2] + ba1) * silu(d[i + 2][j][2] + bg1);
                float y3 = (d[i][j][3] + ba1) * silu(d[i + 2][j][3] + bg1);
                *(unsigned*)(tb + sw_off(k0, m))     = pack_h2(y0, y1);
                *(unsigned*)(tb + sw_off(k0 + 8, m)) = pack_h2(y2, y3);
            }
        }
    }
}

// =================== G2: fp16sw input GEMM (cp.async tile copy) ============
// OUTMODE 0: fp32   1: fp32 + fp16sw copy   2: fp32 + scale*add
template<int OUTMODE>
__global__ void __launch_bounds__(256, 2) gemm_h16(
    const uint4* __restrict__ Wp, const float* __restrict__ bias,
    const uint4* __restrict__ X16, int MTILES,
    float* __restrict__ Y, uint4* __restrict__ Y16,
    const float* __restrict__ addp, const float* __restrict__ addScaleP,
    int S)
{
    __shared__ __align__(16) unsigned char xh[32768];
    const int tid = threadIdx.x;
    const int b = blockIdx.z;
    const int m0 = blockIdx.x * 128;

    // ---- bulk tile copy: global fp16sw -> smem (identical layout) ----
    const uint4* gsrc = X16 + (size_t)(b * MTILES + blockIdx.x) * 2048;
    uint32_t sb = smem_u32(xh);
#pragma unroll
    for (int e = 0; e < 8; e++) {
        int idx = e * 256 + tid;
        asm volatile("cp.async.cg.shared.global [%0], [%1], 16;"
                     :: "r"(sb + idx * 16), "l"(gsrc + idx));
    }
    asm volatile("cp.async.commit_group;" ::: "memory");
    asm volatile("cp.async.wait_group 0;" ::: "memory");
    __syncthreads();

    // ---- mainloop: 128o x 128m x 128k ----
    const int w = tid >> 5, l = tid & 31;
    const int wm = w & 3, wn = w >> 2;
    const int mi = l >> 3, r = l & 7;
    const int k_off = (mi & 1) * 8 + r;
    const int n_off = (mi >> 1) * 8;
    const unsigned mask = ((unsigned)k_off & 7u) << 4;
    const uint32_t xrow = sb + (unsigned)k_off * 256u;

    float d[2][8][4];
#pragma unroll
    for (int i = 0; i < 2; i++)
#pragma unroll
        for (int j = 0; j < 8; j++)
#pragma unroll
            for (int e = 0; e < 4; e++) d[i][j][e] = 0.f;

#pragma unroll
    for (int ks = 0; ks < 8; ks++) {
        uint4 Ah[2];
#pragma unroll
        for (int i = 0; i < 2; i++)
            Ah[i] = Wp[((wm * 2 + i) * 8 + ks) * 32 + l];
        unsigned bh[8][2];
#pragma unroll
        for (int jp = 0; jp < 4; jp++) {
            unsigned col = (unsigned)(wn * 64 + jp * 16 + n_off);
            unsigned r0, r1, r2, r3;
            LDMX4T(r0, r1, r2, r3, xrow + (unsigned)ks * 4096u + ((col * 2u) ^ mask));
            bh[2 * jp][0] = r0; bh[2 * jp][1] = r1;
            bh[2 * jp + 1][0] = r2; bh[2 * jp + 1][1] = r3;
        }
#pragma unroll
        for (int i = 0; i < 2; i++)
#pragma unroll
            for (int j = 0; j < 8; j++)
                MMA_F16(d[i][j], Ah[i], bh[j]);
    }

    // ---- epilogue ----
    float scl = 1.f;
    if (OUTMODE == 2) { if (addScaleP) scl = __ldg(addScaleP); }
    float* Yb = Y + (size_t)b * 128 * S;
    const float* Ab = (OUTMODE == 2) ? (addp + (size_t)b * 128 * S) : nullptr;
    unsigned char* tb = nullptr;
    if (OUTMODE == 1)
        tb = (unsigned char*)(Y16 + (size_t)(b * MTILES + blockIdx.x) * 2048);

#pragma unroll
    for (int i = 0; i < 2; i++) {
        int o0 = wm * 32 + i * 16 + (l >> 2);
        float b0v = __ldg(bias + o0);
        float b1v = __ldg(bias + o0 + 8);
#pragma unroll
        for (int j = 0; j < 8; j++) {
            int ml = wn * 64 + j * 8 + (l & 3) * 2;
            int m = m0 + ml;
            size_t p0 = (size_t)o0 * S + m;
            size_t p1 = (size_t)(o0 + 8) * S + m;
            float y0 = d[i][j][0] + b0v, y1 = d[i][j][1] + b0v;
            float y2 = d[i][j][2] + b1v, y3 = d[i][j][3] + b1v;
            if (OUTMODE == 2) {
                float2 a0 = *(const float2*)(Ab + p0);
                float2 a1 = *(const float2*)(Ab + p1);
                y0 += scl * a0.x; y1 += scl * a0.y;
                y2 += scl * a1.x; y3 += scl * a1.y;
            }
            *(float2*)(Yb + p0) = make_float2(y0, y1);
            *(float2*)(Yb + p1) = make_float2(y2, y3);
            if (OUTMODE == 1) {
                *(unsigned*)(tb + sw_off(o0, ml))     = pack_h2(y0, y1);
                *(unsigned*)(tb + sw_off(o0 + 8, ml)) = pack_h2(y2, y3);
            }
        }
    }
}

// ---------------- fused per-(b,t) cross attention (fp32 SIMT) ---------------
// Reads q/k/v fp32; writes attended as fp16sw tiles for the o-projection.
__global__ void __launch_bounds__(256) attn_k(
    const float* __restrict__ Q, const float* __restrict__ Kb,
    const float* __restrict__ Vb, uint4* __restrict__ Att16,
    const float* __restrict__ basis,
    const float* __restrict__ sscaleP, const float* __restrict__ pscaleP)
{
    extern __shared__ float sm[];
    float* Ks = sm;                  // [128][68]
    float* Qs = Ks + 128 * 68;       // [128][68]
    float* Vs = Qs + 128 * 68;       // [128][65]
    float* Ss = Vs + 128 * 65;       // [64][65]
    const int t = blockIdx.x, b = blockIdx.y;
    const int tid = threadIdx.x;
    const float sscale = __ldg(sscaleP), pscale = __ldg(pscaleP);

    for (int lin = tid; lin < 128 * 64; lin += 256) {
        int c = lin >> 6, kk = lin & 63;
        size_t g = ((size_t)(b * 128 + c) * 128 + t) * 64 + kk;
        Ks[c * 68 + kk] = Kb[g];
        Vs[c * 65 + kk] = Vb[g];
    }
    __syncthreads();

    const int ty = tid >> 4, tx = tid & 15;
    const int ay = tid >> 4, ax = tid & 15;

    for (int f0 = 0; f0 < 512; f0 += 64) {
        for (int lin = tid; lin < 128 * 64; lin += 256) {
            int c = lin >> 6, j = lin & 63;
            Qs[c * 68 + j] = Q[((size_t)(b * 128 + c) * 128 + t) * 512 + f0 + j];
        }
        __syncthreads();

        float acc[4][4] = {};
#pragma unroll 4
        for (int c = 0; c < 128; c++) {
            float4 af = *(const float4*)&Qs[c * 68 + ty * 4];
            float4 bf = *(const float4*)&Ks[c * 68 + tx * 4];
            float av[4] = {af.x, af.y, af.z, af.w};
            float bv[4] = {bf.x, bf.y, bf.z, bf.w};
#pragma unroll
            for (int i = 0; i < 4; i++)
#pragma unroll
                for (int j = 0; j < 4; j++)
                    acc[i][j] = fmaf(av[i], bv[j], acc[i][j]);
        }
#pragma unroll
        for (int i = 0; i < 4; i++)
#pragma unroll
            for (int j = 0; j < 4; j++) {
                int fl = ty * 4 + i, kk = tx * 4 + j;
                Ss[fl * 65 + kk] = acc[i][j] * sscale
                                 + pscale * basis[kk * 512 + f0 + fl];
            }
        __syncthreads();

        {
            int row = tid >> 2, q = tid & 3;
            float* rr = &Ss[row * 65];
            float mx = -3.4e38f;
            for (int i = q; i < 64; i += 4) mx = fmaxf(mx, rr[i]);
            mx = fmaxf(mx, __shfl_xor_sync(0xffffffffu, mx, 1));
            mx = fmaxf(mx, __shfl_xor_sync(0xffffffffu, mx, 2));
            float sum = 0.f;
            for (int i = q; i < 64; i += 4) { float e = expf(rr[i] - mx); rr[i] = e; sum += e; }
            sum += __shfl_xor_sync(0xffffffffu, sum, 1);
            sum += __shfl_xor_sync(0xffffffffu, sum, 2);
            float inv = 1.f / sum;
            for (int i = q; i < 64; i += 4) rr[i] *= inv;
        }
        __syncthreads();

        float at[8][4] = {};
        for (int kk = 0; kk < 64; kk++) {
            float bv[4];
#pragma unroll
            for (int j = 0; j < 4; j++) bv[j] = Ss[(ax * 4 + j) * 65 + kk];
#pragma unroll
            for (int i = 0; i < 8; i++) {
                float av = Vs[(ay * 8 + i) * 65 + kk];
#pragma unroll
                for (int j = 0; j < 4; j++) at[i][j] = fmaf(av, bv[j], at[i][j]);
            }
        }
        // write attended -> fp16sw tile (consumed by o-projection)
        unsigned char* tb = (unsigned char*)(Att16
            + (size_t)(b * 512 + t * 4 + (f0 >> 7)) * 2048);
        int mb = (f0 & 64) + ax * 4;
#pragma unroll
        for (int i = 0; i < 8; i++) {
            int c = ay * 8 + i;
            *(unsigned*)(tb + sw_off(c, mb))     = pack_h2(at[i][0], at[i][1]);
            *(unsigned*)(tb + sw_off(c, mb + 2)) = pack_h2(at[i][2], at[i][3]);
        }
    }
}

// ---------------- launch ----------------------------------------------------
extern "C" void kernel_launch(void* const* d_in, const int* in_sizes, int n_in,
                              void* d_out, int out_size)
{
    const float* latent     = (const float*)d_in[0];
    const float* side       = (const float*)d_in[1];
    const float* basis      = (const float*)d_in[2];
    const float* lp_gamma   = (const float*)d_in[3];
    const float* lp_w       = (const float*)d_in[4];
    const float* lp_b       = (const float*)d_in[5];
    const float* qn_gamma   = (const float*)d_in[6];
    const float* qmlp_in_w  = (const float*)d_in[7];
    const float* qmlp_in_b  = (const float*)d_in[8];
    const float* qmlp_out_w = (const float*)d_in[9];
    const float* qmlp_out_b = (const float*)d_in[10];
    const float* q_w        = (const float*)d_in[11];
    const float* q_b        = (const float*)d_in[12];
    const float* k_w        = (const float*)d_in[13];
    const float* k_b        = (const float*)d_in[14];
    const float* v_w        = (const float*)d_in[15];
    const float* v_b        = (const float*)d_in[16];
    const float* o_w        = (const float*)d_in[17];
    const float* o_b        = (const float*)d_in[18];
    const float* ffn_gamma  = (const float*)d_in[19];
    const float* ffn_in_w   = (const float*)d_in[20];
    const float* ffn_in_b   = (const float*)d_in[21];
    const float* ffn_out_w  = (const float*)d_in[22];
    const float* ffn_out_b  = (const float*)d_in[23];
    const float* score_scale      = (const float*)d_in[24];
    const float* prior_scale      = (const float*)d_in[25];
    const float* query_skip_scale = (const float*)d_in[26];
    float* out = (float*)d_out;

    float *kbuf_p, *vbuf_p, *qh_p, *q_p;
    uint4 *lat16, *A16, *qh16, *att16, *wfrag;
    cudaGetSymbolAddress((void**)&kbuf_p, g_kbuf);
    cudaGetSymbolAddress((void**)&vbuf_p, g_vbuf);
    cudaGetSymbolAddress((void**)&qh_p,   g_qh);
    cudaGetSymbolAddress((void**)&q_p,    g_q);
    cudaGetSymbolAddress((void**)&lat16,  g_lat16);
    cudaGetSymbolAddress((void**)&A16,    g_A16);
    cudaGetSymbolAddress((void**)&qh16,   g_qh16);
    cudaGetSymbolAddress((void**)&att16,  g_att16);
    cudaGetSymbolAddress((void**)&wfrag,  g_Wp);

    const int OFF_LP = 0, OFF_QIN = 64, OFF_QOUT = 192, OFF_Q = 256,
              OFF_K = 320, OFF_V = 384, OFF_O = 448, OFF_FIN = 512, OFF_FOUT = 640;

    WPtrs wp;
    wp.p[0] = lp_w;      wp.p[1] = qmlp_in_w; wp.p[2] = qmlp_out_w;
    wp.p[3] = q_w;       wp.p[4] = k_w;       wp.p[5] = v_w;
    wp.p[6] = o_w;       wp.p[7] = ffn_in_w;  wp.p[8] = ffn_out_w;
    prep_all<<<88, 256>>>(wp, wfrag);

    // latent path: rmsnorm -> lp conv -> silu -> lat16
    gemm_f32in<128><<<dim3(SL / 128, 1, 8), 256>>>(
        wfrag + OFF_LP * 32, lp_b, latent, lp_gamma, lat16, SL);
    // k, v projections (fp16sw in, fp32 out for attention)
    gemm_h16<0><<<dim3(SL / 128, 1, 8), 256>>>(
        wfrag + OFF_K * 32, k_b, lat16, SL >> 7, kbuf_p, nullptr, nullptr, nullptr, SL);
    gemm_h16<0><<<dim3(SL / 128, 1, 8), 256>>>(
        wfrag + OFF_V * 32, v_b, lat16, SL >> 7, vbuf_p, nullptr, nullptr, nullptr, SL);

    // side path: rmsnorm -> qmlp_in -> GLU (in epilogue) -> A16
    gemm_f32in<256><<<dim3(SS / 64, 1, 8), 256>>>(
        wfrag + OFF_QIN * 32, qmlp_in_b, side, qn_gamma, A16, SS);
    // qmlp_out: A16 -> qh fp32 (for skip) + qh16 (for q proj)
    gemm_h16<1><<<dim3(SS / 128, 1, 8), 256>>>(
        wfrag + OFF_QOUT * 32, qmlp_out_b, A16, SS >> 7, qh_p, qh16, nullptr, nullptr, SS);
    // q projection: qh16 -> q fp32
    gemm_h16<0><<<dim3(SS / 128, 1, 8), 256>>>(
        wfrag + OFF_Q * 32, q_b, qh16, SS >> 7, q_p, nullptr, nullptr, nullptr, SS);

    // fused attention -> att16
    cudaFuncSetAttribute(attn_k, cudaFuncAttributeMaxDynamicSharedMemorySize, 119552);
    attn_k<<<dim3(128, 8), 256, 119552>>>(q_p, kbuf_p, vbuf_p, att16, basis,
                                          score_scale, prior_scale);

    // o projection + query skip -> hidden (d_out)
    gemm_h16<2><<<dim3(SS / 128, 1, 8), 256>>>(
        wfrag + OFF_O * 32, o_b, att16, SS >> 7, out, nullptr,
        qh_p, query_skip_scale, SS);

    // ffn: rmsnorm -> ffn_in -> GLU (in epilogue) -> A16
    gemm_f32in<256><<<dim3(SS / 64, 1, 8), 256>>>(
        wfrag + OFF_FIN * 32, ffn_in_b, out, ffn_gamma, A16, SS);
    // ffn_out + residual -> hidden (d_out)
    gemm_h16<2><<<dim3(SS / 128, 1, 8), 256>>>(
        wfrag + OFF_FOUT * 32, ffn_out_b, A16, SS >> 7, out, nullptr,
        out, nullptr, SS);
}

// round 13
// speedup vs baseline: 3.0145x; 1.4596x over previous
#include <cuda_runtime.h>
#include <cuda_fp16.h>
#include <cstdint>
#include <math.h>

// Problem constants: B=8, C=128, T=128, F=512, K=64
static constexpr int SL = 8192;    // latent positions/batch
static constexpr int SS = 65536;   // side positions/batch

// ---------------- scratch (device globals; no cudaMalloc allowed) ----------
__device__ float g_kbuf[8 * 128 * 8192];
__device__ float g_vbuf[8 * 128 * 8192];
__device__ float g_qh[(size_t)8 * 128 * 65536];
__device__ float g_q[(size_t)8 * 128 * 65536];
// fp16 pre-swizzled tile tensors: 32KB tiles of [128 k][128 m]
__device__ uint4 g_lat16[(size_t)8 * 64 * 2048];
__device__ uint4 g_A16[(size_t)8 * 512 * 2048];      // GLU'd swiglu hidden (both MLPs)
__device__ uint4 g_qh16[(size_t)8 * 512 * 2048];
__device__ uint4 g_att16[(size_t)8 * 512 * 2048];
// fp16 weight fragments (A-operand layout for mma.m16n8k16)
__device__ uint4 g_Wp[704 * 32];

// =================== helpers ===================
__device__ __forceinline__ uint32_t smem_u32(const void* p) {
    uint32_t a;
    asm("{ .reg .u64 t; cvta.to.shared.u64 t, %1; cvt.u32.u64 %0, t; }"
        : "=r"(a) : "l"(p));
    return a;
}
__device__ __forceinline__ unsigned pack_h2(float a, float b) {
    __half2 h = __floats2half2_rn(a, b);
    return *(unsigned*)&h;
}
__device__ __forceinline__ float silu(float g) { return g / (1.f + expf(-g)); }
// byte offset inside a 32KB [128k][128m] fp16 tile (256B rows, XOR-swizzled)
__device__ __forceinline__ unsigned sw_off(int k, int mp) {
    return (unsigned)k * 256u + (((unsigned)mp * 2u) ^ (((unsigned)k & 7u) << 4));
}

#define MMA_F16(dd, aa, bb)                                                    \
    asm volatile("mma.sync.aligned.m16n8k16.row.col.f32.f16.f16.f32 "          \
        "{%0,%1,%2,%3}, {%4,%5,%6,%7}, {%8,%9}, {%0,%1,%2,%3};"                \
        : "+f"((dd)[0]), "+f"((dd)[1]), "+f"((dd)[2]), "+f"((dd)[3])           \
        : "r"((aa).x), "r"((aa).y), "r"((aa).z), "r"((aa).w),                  \
          "r"((bb)[0]), "r"((bb)[1]))

#define LDMX4T(b0, b1, b2, b3, addr)                                           \
    asm volatile("ldmatrix.sync.aligned.m8n8.x4.trans.shared.b16 "             \
        "{%0,%1,%2,%3}, [%4];"                                                 \
        : "=r"(b0), "=r"(b1), "=r"(b2), "=r"(b3) : "r"(addr))

// ---------------- single weight-prep kernel (all 9 matrices) ---------------
struct WPtrs { const float* p[9]; };
__constant__ int c_tile_start[10] = {0, 64, 192, 256, 320, 384, 448, 512, 640, 704};

__global__ void __launch_bounds__(256) prep_all(WPtrs wp, uint4* __restrict__ dst)
{
    int gw = (blockIdx.x * 256 + threadIdx.x) >> 5;     // global tile index
    if (gw >= 704) return;
    int mi = 0;
    while (gw >= c_tile_start[mi + 1]) mi++;
    int tile = gw - c_tile_start[mi];
    const float* W = wp.p[mi];
    const int mt = tile >> 3, ks = tile & 7;
    const int l = threadIdx.x & 31;
    const int o = mt * 16 + (l >> 2);
    const int c = ks * 16 + (l & 3) * 2;
    const float* w0 = W + o * 128 + c;
    const float* w1 = W + (o + 8) * 128 + c;
    uint4 H;
    H.x = pack_h2(w0[0], w0[1]);
    H.y = pack_h2(w1[0], w1[1]);
    H.z = pack_h2(w0[8], w0[9]);
    H.w = pack_h2(w1[8], w1[9]);
    dst[gw * 32 + l] = H;
}

// =================== G1: fp32+RMSNorm input GEMM -> fp16sw output ==========
// NOUT=128: lp layer, SILU epilogue -> fp16sw tile.
// NOUT=256: swiglu-in layer, GLU epilogue (a*silu(g)) -> 128-ch fp16sw tile.
template<int NOUT>
__global__ void __launch_bounds__(256, 2) gemm_f32in(
    const uint4* __restrict__ Wp, const float* __restrict__ bias,
    const float* __restrict__ X, const float* __restrict__ gamma,
    uint4* __restrict__ Y16, int S)
{
    constexpr int MT   = (NOUT == 128) ? 128 : 64;
    constexpr int ROWB = MT * 2;
    constexpr int ISUB = NOUT / 64;        // 2 or 4
    constexpr int WARP_M = MT / 2;         // 64 or 32
    constexpr int JQ  = WARP_M / 16;       // 4 or 2
    constexpr int JS  = WARP_M / 8;        // 8 or 4
    constexpr int TPP = 256 / MT;          // rms threads per position

    __shared__ __align__(16) unsigned char xh[128 * ROWB];
    __shared__ float red[256];
    __shared__ float rmss[MT];

    const int tid = threadIdx.x;
    const int b = blockIdx.z;
    const int m0 = blockIdx.x * MT;
    const float* Xb = X + (size_t)b * 128 * S;

    // ---- RMS over channel dim ----
    {
        int p = tid % MT, qd = tid / MT;
        const float* xp = Xb + m0 + p;
        float s = 0.f;
        for (int c = qd; c < 128; c += TPP) { float v = xp[(size_t)c * S]; s = fmaf(v, v, s); }
        red[tid] = s;
        __syncthreads();
        if (tid < MT) {
            float t = 0.f;
#pragma unroll
            for (int e = 0; e < TPP; e++) t += red[tid + e * MT];
            rmss[tid] = rsqrtf(t * (1.f / 128.f) + 1e-6f);
        }
        __syncthreads();
    }

    // ---- convert X tile -> smem fp16 (batched for MLP) ----
    constexpr int TOT2 = 128 * MT / 2;                 // float2 elements
    for (int base = 0; base < TOT2; base += 2048) {
        float2 vv[8];
#pragma unroll
        for (int e = 0; e < 8; e++) {
            int u = base + e * 256 + tid;
            int k = u / (MT / 2), j = u % (MT / 2);
            vv[e] = *(const float2*)(Xb + (size_t)k * S + m0 + 2 * j);
        }
#pragma unroll
        for (int e = 0; e < 8; e++) {
            int u = base + e * 256 + tid;
            int k = u / (MT / 2), j = u % (MT / 2);
            float gm = __ldg(gamma + k);
            float2 v = vv[e];
            v.x *= rmss[2 * j] * gm;
            v.y *= rmss[2 * j + 1] * gm;
            unsigned off = (unsigned)k * ROWB
                         + (((unsigned)(j * 4)) ^ (((unsigned)k & 7u) << 4));
            *(unsigned*)(xh + off) = pack_h2(v.x, v.y);
        }
    }
    __syncthreads();

    // ---- mainloop ----
    const int w = tid >> 5, l = tid & 31;
    const int wm = w & 3, wn = w >> 2;
    const int mi = l >> 3, r = l & 7;
    const int k_off = (mi & 1) * 8 + r;
    const int n_off = (mi >> 1) * 8;
    const unsigned mask = ((unsigned)k_off & 7u) << 4;
    const uint32_t xrow = smem_u32(xh) + (unsigned)k_off * ROWB;

    float d[ISUB][JS][4];
#pragma unroll
    for (int i = 0; i < ISUB; i++)
#pragma unroll
        for (int j = 0; j < JS; j++)
#pragma unroll
            for (int e = 0; e < 4; e++) d[i][j][e] = 0.f;

#pragma unroll
    for (int ks = 0; ks < 8; ks++) {
        uint4 Ah[ISUB];
#pragma unroll
        for (int i = 0; i < ISUB; i++) {
            int mt = (NOUT == 256 && i >= 2) ? (8 + wm * 2 + (i - 2)) : (wm * 2 + i);
            Ah[i] = Wp[(mt * 8 + ks) * 32 + l];
        }
        unsigned bh[JS][2];
#pragma unroll
        for (int jp = 0; jp < JQ; jp++) {
            unsigned col = (unsigned)(wn * WARP_M + jp * 16 + n_off);
            unsigned r0, r1, r2, r3;
            LDMX4T(r0, r1, r2, r3, xrow + (unsigned)ks * 16u * ROWB + ((col * 2u) ^ mask));
            bh[2 * jp][0] = r0; bh[2 * jp][1] = r1;
            bh[2 * jp + 1][0] = r2; bh[2 * jp + 1][1] = r3;
        }
#pragma unroll
        for (int i = 0; i < ISUB; i++)
#pragma unroll
            for (int j = 0; j < JS; j++)
                MMA_F16(d[i][j], Ah[i], bh[j]);
    }

    // ---- epilogue -> fp16sw tile ----
    const int MTILES = S >> 7;
    unsigned char* tb = (unsigned char*)(Y16 + (size_t)(b * MTILES + (m0 >> 7)) * 2048);
    const int mpb = m0 & 127;                          // 0 or 64
#pragma unroll
    for (int i = 0; i < 2; i++) {
        int k0 = wm * 32 + i * 16 + (l >> 2);
        if (NOUT == 128) {
            float b0 = __ldg(bias + k0), b1 = __ldg(bias + k0 + 8);
#pragma unroll
            for (int j = 0; j < JS; j++) {
                int m = mpb + wn * WARP_M + j * 8 + (l & 3) * 2;
                float y0 = silu(d[i][j][0] + b0), y1 = silu(d[i][j][1] + b0);
                float y2 = silu(d[i][j][2] + b1), y3 = silu(d[i][j][3] + b1);
                *(unsigned*)(tb + sw_off(k0, m))     = pack_h2(y0, y1);
                *(unsigned*)(tb + sw_off(k0 + 8, m)) = pack_h2(y2, y3);
            }
        } else {
            float ba0 = __ldg(bias + k0), ba1 = __ldg(bias + k0 + 8);
            float bg0 = __ldg(bias + 128 + k0), bg1 = __ldg(bias + 128 + k0 + 8);
#pragma unroll
            for (int j = 0; j < JS; j++) {
                int m = mpb + wn * WARP_M + j * 8 + (l & 3) * 2;
                float y0 = (d[i][j][0] + ba0) * silu(d[i + 2][j][0] + bg0);
                float y1 = (d[i][j][1] + ba0) * silu(d[i + 2][j][1] + bg0);
                float y2 = (d[i][j][2] + ba1) * silu(d[i + 2][j][2] + bg1);
                float y3 = (d[i][j][3] + ba1) * silu(d[i + 2][j][3] + bg1);
                *(unsigned*)(tb + sw_off(k0, m))     = pack_h2(y0, y1);
                *(unsigned*)(tb + sw_off(k0 + 8, m)) = pack_h2(y2, y3);
            }
        }
    }
}

// =================== G2: fp16sw input GEMM (cp.async tile copy) ============
// OUTMODE 0: fp32   1: fp32 + fp16sw copy   2: fp32 + scale*add
template<int OUTMODE>
__global__ void __launch_bounds__(256, 2) gemm_h16(
    const uint4* __restrict__ Wp, const float* __restrict__ bias,
    const uint4* __restrict__ X16, int MTILES,
    float* __restrict__ Y, uint4* __restrict__ Y16,
    const float* __restrict__ addp, const float* __restrict__ addScaleP,
    int S)
{
    __shared__ __align__(16) unsigned char xh[32768];
    const int tid = threadIdx.x;
    const int b = blockIdx.z;
    const int m0 = blockIdx.x * 128;

    // ---- bulk tile copy: global fp16sw -> smem (identical layout) ----
    const uint4* gsrc = X16 + (size_t)(b * MTILES + blockIdx.x) * 2048;
    uint32_t sb = smem_u32(xh);
#pragma unroll
    for (int e = 0; e < 8; e++) {
        int idx = e * 256 + tid;
        asm volatile("cp.async.cg.shared.global [%0], [%1], 16;"
                     :: "r"(sb + idx * 16), "l"(gsrc + idx));
    }
    asm volatile("cp.async.commit_group;" ::: "memory");
    asm volatile("cp.async.wait_group 0;" ::: "memory");
    __syncthreads();

    // ---- mainloop: 128o x 128m x 128k ----
    const int w = tid >> 5, l = tid & 31;
    const int wm = w & 3, wn = w >> 2;
    const int mi = l >> 3, r = l & 7;
    const int k_off = (mi & 1) * 8 + r;
    const int n_off = (mi >> 1) * 8;
    const unsigned mask = ((unsigned)k_off & 7u) << 4;
    const uint32_t xrow = sb + (unsigned)k_off * 256u;

    float d[2][8][4];
#pragma unroll
    for (int i = 0; i < 2; i++)
#pragma unroll
        for (int j = 0; j < 8; j++)
#pragma unroll
            for (int e = 0; e < 4; e++) d[i][j][e] = 0.f;

#pragma unroll
    for (int ks = 0; ks < 8; ks++) {
        uint4 Ah[2];
#pragma unroll
        for (int i = 0; i < 2; i++)
            Ah[i] = Wp[((wm * 2 + i) * 8 + ks) * 32 + l];
        unsigned bh[8][2];
#pragma unroll
        for (int jp = 0; jp < 4; jp++) {
            unsigned col = (unsigned)(wn * 64 + jp * 16 + n_off);
            unsigned r0, r1, r2, r3;
            LDMX4T(r0, r1, r2, r3, xrow + (unsigned)ks * 4096u + ((col * 2u) ^ mask));
            bh[2 * jp][0] = r0; bh[2 * jp][1] = r1;
            bh[2 * jp + 1][0] = r2; bh[2 * jp + 1][1] = r3;
        }
#pragma unroll
        for (int i = 0; i < 2; i++)
#pragma unroll
            for (int j = 0; j < 8; j++)
                MMA_F16(d[i][j], Ah[i], bh[j]);
    }

    // ---- epilogue ----
    float scl = 1.f;
    if (OUTMODE == 2) { if (addScaleP) scl = __ldg(addScaleP); }
    float* Yb = Y + (size_t)b * 128 * S;
    const float* Ab = (OUTMODE == 2) ? (addp + (size_t)b * 128 * S) : nullptr;
    unsigned char* tb = nullptr;
    if (OUTMODE == 1)
        tb = (unsigned char*)(Y16 + (size_t)(b * MTILES + blockIdx.x) * 2048);

#pragma unroll
    for (int i = 0; i < 2; i++) {
        int o0 = wm * 32 + i * 16 + (l >> 2);
        float b0v = __ldg(bias + o0);
        float b1v = __ldg(bias + o0 + 8);
#pragma unroll
        for (int j = 0; j < 8; j++) {
            int ml = wn * 64 + j * 8 + (l & 3) * 2;
            int m = m0 + ml;
            size_t p0 = (size_t)o0 * S + m;
            size_t p1 = (size_t)(o0 + 8) * S + m;
            float y0 = d[i][j][0] + b0v, y1 = d[i][j][1] + b0v;
            float y2 = d[i][j][2] + b1v, y3 = d[i][j][3] + b1v;
            if (OUTMODE == 2) {
                float2 a0 = *(const float2*)(Ab + p0);
                float2 a1 = *(const float2*)(Ab + p1);
                y0 += scl * a0.x; y1 += scl * a0.y;
                y2 += scl * a1.x; y3 += scl * a1.y;
            }
            *(float2*)(Yb + p0) = make_float2(y0, y1);
            *(float2*)(Yb + p1) = make_float2(y2, y3);
            if (OUTMODE == 1) {
                *(unsigned*)(tb + sw_off(o0, ml))     = pack_h2(y0, y1);
                *(unsigned*)(tb + sw_off(o0 + 8, ml)) = pack_h2(y2, y3);
            }
        }
    }
}

// ---------------- fused per-(b,t) cross attention (fp32 SIMT) ---------------
// Reads q/k/v fp32; writes attended as fp16sw tiles for the o-projection.
__global__ void __launch_bounds__(256) attn_k(
    const float* __restrict__ Q, const float* __restrict__ Kb,
    const float* __restrict__ Vb, uint4* __restrict__ Att16,
    const float* __restrict__ basis,
    const float* __restrict__ sscaleP, const float* __restrict__ pscaleP)
{
    extern __shared__ float sm[];
    float* Ks = sm;                  // [128][68]
    float* Qs = Ks + 128 * 68;       // [128][68]
    float* Vs = Qs + 128 * 68;       // [128][65]
    float* Ss = Vs + 128 * 65;       // [64][65]
    const int t = blockIdx.x, b = blockIdx.y;
    const int tid = threadIdx.x;
    const float sscale = __ldg(sscaleP), pscale = __ldg(pscaleP);

    for (int lin = tid; lin < 128 * 64; lin += 256) {
        int c = lin >> 6, kk = lin & 63;
        size_t g = ((size_t)(b * 128 + c) * 128 + t) * 64 + kk;
        Ks[c * 68 + kk] = Kb[g];
        Vs[c * 65 + kk] = Vb[g];
    }
    __syncthreads();

    const int ty = tid >> 4, tx = tid & 15;
    const int ay = tid >> 4, ax = tid & 15;

    for (int f0 = 0; f0 < 512; f0 += 64) {
        for (int lin = tid; lin < 128 * 64; lin += 256) {
            int c = lin >> 6, j = lin & 63;
            Qs[c * 68 + j] = Q[((size_t)(b * 128 + c) * 128 + t) * 512 + f0 + j];
        }
        __syncthreads();

        float acc[4][4] = {};
#pragma unroll 4
        for (int c = 0; c < 128; c++) {
            float4 af = *(const float4*)&Qs[c * 68 + ty * 4];
            float4 bf = *(const float4*)&Ks[c * 68 + tx * 4];
            float av[4] = {af.x, af.y, af.z, af.w};
            float bv[4] = {bf.x, bf.y, bf.z, bf.w};
#pragma unroll
            for (int i = 0; i < 4; i++)
#pragma unroll
                for (int j = 0; j < 4; j++)
                    acc[i][j] = fmaf(av[i], bv[j], acc[i][j]);
        }
#pragma unroll
        for (int i = 0; i < 4; i++)
#pragma unroll
            for (int j = 0; j < 4; j++) {
                int fl = ty * 4 + i, kk = tx * 4 + j;
                Ss[fl * 65 + kk] = acc[i][j] * sscale
                                 + pscale * basis[kk * 512 + f0 + fl];
            }
        __syncthreads();

        {
            int row = tid >> 2, q = tid & 3;
            float* rr = &Ss[row * 65];
            float mx = -3.4e38f;
            for (int i = q; i < 64; i += 4) mx = fmaxf(mx, rr[i]);
            mx = fmaxf(mx, __shfl_xor_sync(0xffffffffu, mx, 1));
            mx = fmaxf(mx, __shfl_xor_sync(0xffffffffu, mx, 2));
            float sum = 0.f;
            for (int i = q; i < 64; i += 4) { float e = expf(rr[i] - mx); rr[i] = e; sum += e; }
            sum += __shfl_xor_sync(0xffffffffu, sum, 1);
            sum += __shfl_xor_sync(0xffffffffu, sum, 2);
            float inv = 1.f / sum;
            for (int i = q; i < 64; i += 4) rr[i] *= inv;
        }
        __syncthreads();

        float at[8][4] = {};
        for (int kk = 0; kk < 64; kk++) {
            float bv[4];
#pragma unroll
            for (int j = 0; j < 4; j++) bv[j] = Ss[(ax * 4 + j) * 65 + kk];
#pragma unroll
            for (int i = 0; i < 8; i++) {
                float av = Vs[(ay * 8 + i) * 65 + kk];
#pragma unroll
                for (int j = 0; j < 4; j++) at[i][j] = fmaf(av, bv[j], at[i][j]);
            }
        }
        // write attended -> fp16sw tile (consumed by o-projection)
        unsigned char* tb = (unsigned char*)(Att16
            + (size_t)(b * 512 + t * 4 + (f0 >> 7)) * 2048);
        int mb = (f0 & 64) + ax * 4;
#pragma unroll
        for (int i = 0; i < 8; i++) {
            int c = ay * 8 + i;
            *(unsigned*)(tb + sw_off(c, mb))     = pack_h2(at[i][0], at[i][1]);
            *(unsigned*)(tb + sw_off(c, mb + 2)) = pack_h2(at[i][2], at[i][3]);
        }
    }
}

// ---------------- launch ----------------------------------------------------
extern "C" void kernel_launch(void* const* d_in, const int* in_sizes, int n_in,
                              void* d_out, int out_size)
{
    const float* latent     = (const float*)d_in[0];
    const float* side       = (const float*)d_in[1];
    const float* basis      = (const float*)d_in[2];
    const float* lp_gamma   = (const float*)d_in[3];
    const float* lp_w       = (const float*)d_in[4];
    const float* lp_b       = (const float*)d_in[5];
    const float* qn_gamma   = (const float*)d_in[6];
    const float* qmlp_in_w  = (const float*)d_in[7];
    const float* qmlp_in_b  = (const float*)d_in[8];
    const float* qmlp_out_w = (const float*)d_in[9];
    const float* qmlp_out_b = (const float*)d_in[10];
    const float* q_w        = (const float*)d_in[11];
    const float* q_b        = (const float*)d_in[12];
    const float* k_w        = (const float*)d_in[13];
    const float* k_b        = (const float*)d_in[14];
    const float* v_w        = (const float*)d_in[15];
    const float* v_b        = (const float*)d_in[16];
    const float* o_w        = (const float*)d_in[17];
    const float* o_b        = (const float*)d_in[18];
    const float* ffn_gamma  = (const float*)d_in[19];
    const float* ffn_in_w   = (const float*)d_in[20];
    const float* ffn_in_b   = (const float*)d_in[21];
    const float* ffn_out_w  = (const float*)d_in[22];
    const float* ffn_out_b  = (const float*)d_in[23];
    const float* score_scale      = (const float*)d_in[24];
    const float* prior_scale      = (const float*)d_in[25];
    const float* query_skip_scale = (const float*)d_in[26];
    float* out = (float*)d_out;

    float *kbuf_p, *vbuf_p, *qh_p, *q_p;
    uint4 *lat16, *A16, *qh16, *att16, *wfrag;
    cudaGetSymbolAddress((void**)&kbuf_p, g_kbuf);
    cudaGetSymbolAddress((void**)&vbuf_p, g_vbuf);
    cudaGetSymbolAddress((void**)&qh_p,   g_qh);
    cudaGetSymbolAddress((void**)&q_p,    g_q);
    cudaGetSymbolAddress((void**)&lat16,  g_lat16);
    cudaGetSymbolAddress((void**)&A16,    g_A16);
    cudaGetSymbolAddress((void**)&qh16,   g_qh16);
    cudaGetSymbolAddress((void**)&att16,  g_att16);
    cudaGetSymbolAddress((void**)&wfrag,  g_Wp);

    const int OFF_LP = 0, OFF_QIN = 64, OFF_QOUT = 192, OFF_Q = 256,
              OFF_K = 320, OFF_V = 384, OFF_O = 448, OFF_FIN = 512, OFF_FOUT = 640;

    WPtrs wp;
    wp.p[0] = lp_w;      wp.p[1] = qmlp_in_w; wp.p[2] = qmlp_out_w;
    wp.p[3] = q_w;       wp.p[4] = k_w;       wp.p[5] = v_w;
    wp.p[6] = o_w;       wp.p[7] = ffn_in_w;  wp.p[8] = ffn_out_w;
    prep_all<<<88, 256>>>(wp, wfrag);

    // latent path: rmsnorm -> lp conv -> silu -> lat16
    gemm_f32in<128><<<dim3(SL / 128, 1, 8), 256>>>(
        wfrag + OFF_LP * 32, lp_b, latent, lp_gamma, lat16, SL);
    // k, v projections (fp16sw in, fp32 out for attention)
    gemm_h16<0><<<dim3(SL / 128, 1, 8), 256>>>(
        wfrag + OFF_K * 32, k_b, lat16, SL >> 7, kbuf_p, nullptr, nullptr, nullptr, SL);
    gemm_h16<0><<<dim3(SL / 128, 1, 8), 256>>>(
        wfrag + OFF_V * 32, v_b, lat16, SL >> 7, vbuf_p, nullptr, nullptr, nullptr, SL);

    // side path: rmsnorm -> qmlp_in -> GLU (in epilogue) -> A16
    gemm_f32in<256><<<dim3(SS / 64, 1, 8), 256>>>(
        wfrag + OFF_QIN * 32, qmlp_in_b, side, qn_gamma, A16, SS);
    // qmlp_out: A16 -> qh fp32 (for skip) + qh16 (for q proj)
    gemm_h16<1><<<dim3(SS / 128, 1, 8), 256>>>(
        wfrag + OFF_QOUT * 32, qmlp_out_b, A16, SS >> 7, qh_p, qh16, nullptr, nullptr, SS);
    // q projection: qh16 -> q fp32
    gemm_h16<0><<<dim3(SS / 128, 1, 8), 256>>>(
        wfrag + OFF_Q * 32, q_b, qh16, SS >> 7, q_p, nullptr, nullptr, nullptr, SS);

    // fused attention -> att16
    cudaFuncSetAttribute(attn_k, cudaFuncAttributeMaxDynamicSharedMemorySize, 119552);
    attn_k<<<dim3(128, 8), 256, 119552>>>(q_p, kbuf_p, vbuf_p, att16, basis,
                                          score_scale, prior_scale);

    // o projection + query skip -> hidden (d_out)
    gemm_h16<2><<<dim3(SS / 128, 1, 8), 256>>>(
        wfrag + OFF_O * 32, o_b, att16, SS >> 7, out, nullptr,
        qh_p, query_skip_scale, SS);

    // ffn: rmsnorm -> ffn_in -> GLU (in epilogue) -> A16
    gemm_f32in<256><<<dim3(SS / 64, 1, 8), 256>>>(
        wfrag + OFF_FIN * 32, ffn_in_b, out, ffn_gamma, A16, SS);
    // ffn_out + residual -> hidden (d_out)
    gemm_h16<2><<<dim3(SS / 128, 1, 8), 256>>>(
        wfrag + OFF_FOUT * 32, ffn_out_b, A16, SS >> 7, out, nullptr,
        out, nullptr, SS);
}

// round 15
// speedup vs baseline: 3.0312x; 1.0055x over previous
#include <cuda_runtime.h>
#include <cuda_fp16.h>
#include <cstdint>
#include <math.h>

// Problem constants: B=8, C=128, T=128, F=512, K=64
static constexpr int SL = 8192;    // latent positions/batch
static constexpr int SS = 65536;   // side positions/batch

// ---------------- scratch (device globals; no cudaMalloc allowed) ----------
__device__ float g_kbuf[8 * 128 * 8192];
__device__ float g_vbuf[8 * 128 * 8192];
__device__ float g_qh[(size_t)8 * 128 * 65536];
__device__ float g_q[(size_t)8 * 128 * 65536];
// fp16 pre-swizzled tile tensors: 32KB tiles of [128 k][128 m]
__device__ uint4 g_lat16[(size_t)8 * 64 * 2048];
__device__ uint4 g_A16[(size_t)8 * 512 * 2048];      // GLU'd swiglu hidden (both MLPs)
__device__ uint4 g_qh16[(size_t)8 * 512 * 2048];
__device__ uint4 g_att16[(size_t)8 * 512 * 2048];
// fp16 weight fragments (A-operand layout for mma.m16n8k16)
__device__ uint4 g_Wp[704 * 32];

// =================== helpers ===================
__device__ __forceinline__ uint32_t smem_u32(const void* p) {
    uint32_t a;
    asm("{ .reg .u64 t; cvta.to.shared.u64 t, %1; cvt.u32.u64 %0, t; }"
        : "=r"(a) : "l"(p));
    return a;
}
__device__ __forceinline__ unsigned pack_h2(float a, float b) {
    __half2 h = __floats2half2_rn(a, b);
    return *(unsigned*)&h;
}
// FFMA-only exp: 2^round(t) * P(frac), rel err ~2.4e-6, no MUFU
__device__ __forceinline__ float fast_exp(float x)
{
    x = fminf(fmaxf(x, -87.f), 88.f);
    float t = x * 1.4426950408889634f;
    float z = t + 12582912.f;                  // 2^23+2^22 round-to-nearest magic
    int   i = __float_as_int(z) - 0x4B400000;  // round(t)
    float f = t - (z - 12582912.f);            // f in [-0.5, 0.5]
    float p =             1.33335581e-3f;
    p = fmaf(p, f, 9.61812911e-3f);
    p = fmaf(p, f, 5.55041087e-2f);
    p = fmaf(p, f, 2.40226507e-1f);
    p = fmaf(p, f, 6.93147181e-1f);
    p = fmaf(p, f, 1.0f);
    return __int_as_float(__float_as_int(p) + (i << 23));
}
// FFMA-only reciprocal: bit-trick seed + 2 Newton steps, rel err ~1.3e-6
__device__ __forceinline__ float fast_rcp(float d)
{
    float r = __int_as_float(0x7EF311C3 - __float_as_int(d));
    r = r * (2.f - d * r);
    r = r * (2.f - d * r);
    return r;
}
__device__ __forceinline__ float silu(float g) {
    return g * fast_rcp(1.f + fast_exp(-g));
}
// byte offset inside a 32KB [128k][128m] fp16 tile (256B rows, XOR-swizzled)
__device__ __forceinline__ unsigned sw_off(int k, int mp) {
    return (unsigned)k * 256u + (((unsigned)mp * 2u) ^ (((unsigned)k & 7u) << 4));
}

#define MMA_F16(dd, aa, bb)                                                    \
    asm volatile("mma.sync.aligned.m16n8k16.row.col.f32.f16.f16.f32 "          \
        "{%0,%1,%2,%3}, {%4,%5,%6,%7}, {%8,%9}, {%0,%1,%2,%3};"                \
        : "+f"((dd)[0]), "+f"((dd)[1]), "+f"((dd)[2]), "+f"((dd)[3])           \
        : "r"((aa).x), "r"((aa).y), "r"((aa).z), "r"((aa).w),                  \
          "r"((bb)[0]), "r"((bb)[1]))

#define LDMX4T(b0, b1, b2, b3, addr)                                           \
    asm volatile("ldmatrix.sync.aligned.m8n8.x4.trans.shared.b16 "             \
        "{%0,%1,%2,%3}, [%4];"                                                 \
        : "=r"(b0), "=r"(b1), "=r"(b2), "=r"(b3) : "r"(addr))

// ---------------- single weight-prep kernel (all 9 matrices) ---------------
struct WPtrs { const float* p[9]; };
__constant__ int c_tile_start[10] = {0, 64, 192, 256, 320, 384, 448, 512, 640, 704};

__global__ void __launch_bounds__(256) prep_all(WPtrs wp, uint4* __restrict__ dst)
{
    int gw = (blockIdx.x * 256 + threadIdx.x) >> 5;     // global tile index
    if (gw >= 704) return;
    int mi = 0;
    while (gw >= c_tile_start[mi + 1]) mi++;
    int tile = gw - c_tile_start[mi];
    const float* W = wp.p[mi];
    const int mt = tile >> 3, ks = tile & 7;
    const int l = threadIdx.x & 31;
    const int o = mt * 16 + (l >> 2);
    const int c = ks * 16 + (l & 3) * 2;
    const float* w0 = W + o * 128 + c;
    const float* w1 = W + (o + 8) * 128 + c;
    uint4 H;
    H.x = pack_h2(w0[0], w0[1]);
    H.y = pack_h2(w1[0], w1[1]);
    H.z = pack_h2(w0[8], w0[9]);
    H.w = pack_h2(w1[8], w1[9]);
    dst[gw * 32 + l] = H;
}

// =================== G1: fp32+RMSNorm input GEMM -> fp16sw output ==========
// NOUT=128: lp layer, SILU epilogue -> fp16sw tile.
// NOUT=256: swiglu-in layer, GLU epilogue (a*silu(g)) -> 128-ch fp16sw tile.
template<int NOUT>
__global__ void __launch_bounds__(256, 2) gemm_f32in(
    const uint4* __restrict__ Wp, const float* __restrict__ bias,
    const float* __restrict__ X, const float* __restrict__ gamma,
    uint4* __restrict__ Y16, int S)
{
    constexpr int MT   = (NOUT == 128) ? 128 : 64;
    constexpr int ROWB = MT * 2;
    constexpr int ISUB = NOUT / 64;        // 2 or 4
    constexpr int WARP_M = MT / 2;         // 64 or 32
    constexpr int JQ  = WARP_M / 16;       // 4 or 2
    constexpr int JS  = WARP_M / 8;        // 8 or 4
    constexpr int TPP = 256 / MT;          // rms threads per position

    __shared__ __align__(16) unsigned char xh[128 * ROWB];
    __shared__ float red[256];
    __shared__ float rmss[MT];

    const int tid = threadIdx.x;
    const int b = blockIdx.z;
    const int m0 = blockIdx.x * MT;
    const float* Xb = X + (size_t)b * 128 * S;

    // ---- RMS over channel dim ----
    {
        int p = tid % MT, qd = tid / MT;
        const float* xp = Xb + m0 + p;
        float s = 0.f;
        for (int c = qd; c < 128; c += TPP) { float v = xp[(size_t)c * S]; s = fmaf(v, v, s); }
        red[tid] = s;
        __syncthreads();
        if (tid < MT) {
            float t = 0.f;
#pragma unroll
            for (int e = 0; e < TPP; e++) t += red[tid + e * MT];
            rmss[tid] = rsqrtf(t * (1.f / 128.f) + 1e-6f);
        }
        __syncthreads();
    }

    // ---- convert X tile -> smem fp16 (batched for MLP) ----
    constexpr int TOT2 = 128 * MT / 2;                 // float2 elements
    for (int base = 0; base < TOT2; base += 2048) {
        float2 vv[8];
#pragma unroll
        for (int e = 0; e < 8; e++) {
            int u = base + e * 256 + tid;
            int k = u / (MT / 2), j = u % (MT / 2);
            vv[e] = *(const float2*)(Xb + (size_t)k * S + m0 + 2 * j);
        }
#pragma unroll
        for (int e = 0; e < 8; e++) {
            int u = base + e * 256 + tid;
            int k = u / (MT / 2), j = u % (MT / 2);
            float gm = __ldg(gamma + k);
            float2 v = vv[e];
            v.x *= rmss[2 * j] * gm;
            v.y *= rmss[2 * j + 1] * gm;
            unsigned off = (unsigned)k * ROWB
                         + (((unsigned)(j * 4)) ^ (((unsigned)k & 7u) << 4));
            *(unsigned*)(xh + off) = pack_h2(v.x, v.y);
        }
    }
    __syncthreads();

    // ---- mainloop ----
    const int w = tid >> 5, l = tid & 31;
    const int wm = w & 3, wn = w >> 2;
    const int mi = l >> 3, r = l & 7;
    const int k_off = (mi & 1) * 8 + r;
    const int n_off = (mi >> 1) * 8;
    const unsigned mask = ((unsigned)k_off & 7u) << 4;
    const uint32_t xrow = smem_u32(xh) + (unsigned)k_off * ROWB;

    float d[ISUB][JS][4];
#pragma unroll
    for (int i = 0; i < ISUB; i++)
#pragma unroll
        for (int j = 0; j < JS; j++)
#pragma unroll
            for (int e = 0; e < 4; e++) d[i][j][e] = 0.f;

#pragma unroll
    for (int ks = 0; ks < 8; ks++) {
        uint4 Ah[ISUB];
#pragma unroll
        for (int i = 0; i < ISUB; i++) {
            int mt = (NOUT == 256 && i >= 2) ? (8 + wm * 2 + (i - 2)) : (wm * 2 + i);
            Ah[i] = Wp[(mt * 8 + ks) * 32 + l];
        }
        unsigned bh[JS][2];
#pragma unroll
        for (int jp = 0; jp < JQ; jp++) {
            unsigned col = (unsigned)(wn * WARP_M + jp * 16 + n_off);
            unsigned r0, r1, r2, r3;
            LDMX4T(r0, r1, r2, r3, xrow + (unsigned)ks * 16u * ROWB + ((col * 2u) ^ mask));
            bh[2 * jp][0] = r0; bh[2 * jp][1] = r1;
            bh[2 * jp + 1][0] = r2; bh[2 * jp + 1][1] = r3;
        }
#pragma unroll
        for (int i = 0; i < ISUB; i++)
#pragma unroll
            for (int j = 0; j < JS; j++)
                MMA_F16(d[i][j], Ah[i], bh[j]);
    }

    // ---- epilogue -> fp16sw tile ----
    const int MTILES = S >> 7;
    unsigned char* tb = (unsigned char*)(Y16 + (size_t)(b * MTILES + (m0 >> 7)) * 2048);
    const int mpb = m0 & 127;                          // 0 or 64
#pragma unroll
    for (int i = 0; i < 2; i++) {
        int k0 = wm * 32 + i * 16 + (l >> 2);
        if (NOUT == 128) {
            float b0 = __ldg(bias + k0), b1 = __ldg(bias + k0 + 8);
#pragma unroll
            for (int j = 0; j < JS; j++) {
                int m = mpb + wn * WARP_M + j * 8 + (l & 3) * 2;
                float y0 = silu(d[i][j][0] + b0), y1 = silu(d[i][j][1] + b0);
                float y2 = silu(d[i][j][2] + b1), y3 = silu(d[i][j][3] + b1);
                *(unsigned*)(tb + sw_off(k0, m))     = pack_h2(y0, y1);
                *(unsigned*)(tb + sw_off(k0 + 8, m)) = pack_h2(y2, y3);
            }
        } else {
            float ba0 = __ldg(bias + k0), ba1 = __ldg(bias + k0 + 8);
            float bg0 = __ldg(bias + 128 + k0), bg1 = __ldg(bias + 128 + k0 + 8);
#pragma unroll
            for (int j = 0; j < JS; j++) {
                int m = mpb + wn * WARP_M + j * 8 + (l & 3) * 2;
                float y0 = (d[i][j][0] + ba0) * silu(d[i + 2][j][0] + bg0);
                float y1 = (d[i][j][1] + ba0) * silu(d[i + 2][j][1] + bg0);
                float y2 = (d[i][j][2] + ba1) * silu(d[i + 2][j][2] + bg1);
                float y3 = (d[i][j][3] + ba1) * silu(d[i + 2][j][3] + bg1);
                *(unsigned*)(tb + sw_off(k0, m))     = pack_h2(y0, y1);
                *(unsigned*)(tb + sw_off(k0 + 8, m)) = pack_h2(y2, y3);
            }
        }
    }
}

// =================== G2: fp16sw input GEMM (cp.async tile copy) ============
// OUTMODE 0: fp32   1: fp32 + fp16sw copy   2: fp32 + scale*add
template<int OUTMODE>
__global__ void __launch_bounds__(256, 2) gemm_h16(
    const uint4* __restrict__ Wp, const float* __restrict__ bias,
    const uint4* __restrict__ X16, int MTILES,
    float* __restrict__ Y, uint4* __restrict__ Y16,
    const float* __restrict__ addp, const float* __restrict__ addScaleP,
    int S)
{
    __shared__ __align__(16) unsigned char xh[32768];
    const int tid = threadIdx.x;
    const int b = blockIdx.z;
    const int m0 = blockIdx.x * 128;

    // ---- bulk tile copy: global fp16sw -> smem (identical layout) ----
    const uint4* gsrc = X16 + (size_t)(b * MTILES + blockIdx.x) * 2048;
    uint32_t sb = smem_u32(xh);
#pragma unroll
    for (int e = 0; e < 8; e++) {
        int idx = e * 256 + tid;
        asm volatile("cp.async.cg.shared.global [%0], [%1], 16;"
                     :: "r"(sb + idx * 16), "l"(gsrc + idx));
    }
    asm volatile("cp.async.commit_group;" ::: "memory");
    asm volatile("cp.async.wait_group 0;" ::: "memory");
    __syncthreads();

    // ---- mainloop: 128o x 128m x 128k ----
    const int w = tid >> 5, l = tid & 31;
    const int wm = w & 3, wn = w >> 2;
    const int mi = l >> 3, r = l & 7;
    const int k_off = (mi & 1) * 8 + r;
    const int n_off = (mi >> 1) * 8;
    const unsigned mask = ((unsigned)k_off & 7u) << 4;
    const uint32_t xrow = sb + (unsigned)k_off * 256u;

    float d[2][8][4];
#pragma unroll
    for (int i = 0; i < 2; i++)
#pragma unroll
        for (int j = 0; j < 8; j++)
#pragma unroll
            for (int e = 0; e < 4; e++) d[i][j][e] = 0.f;

#pragma unroll
    for (int ks = 0; ks < 8; ks++) {
        uint4 Ah[2];
#pragma unroll
        for (int i = 0; i < 2; i++)
            Ah[i] = Wp[((wm * 2 + i) * 8 + ks) * 32 + l];
        unsigned bh[8][2];
#pragma unroll
        for (int jp = 0; jp < 4; jp++) {
            unsigned col = (unsigned)(wn * 64 + jp * 16 + n_off);
            unsigned r0, r1, r2, r3;
            LDMX4T(r0, r1, r2, r3, xrow + (unsigned)ks * 4096u + ((col * 2u) ^ mask));
            bh[2 * jp][0] = r0; bh[2 * jp][1] = r1;
            bh[2 * jp + 1][0] = r2; bh[2 * jp + 1][1] = r3;
        }
#pragma unroll
        for (int i = 0; i < 2; i++)
#pragma unroll
            for (int j = 0; j < 8; j++)
                MMA_F16(d[i][j], Ah[i], bh[j]);
    }

    // ---- epilogue ----
    float scl = 1.f;
    if (OUTMODE == 2) { if (addScaleP) scl = __ldg(addScaleP); }
    float* Yb = Y + (size_t)b * 128 * S;
    const float* Ab = (OUTMODE == 2) ? (addp + (size_t)b * 128 * S) : nullptr;
    unsigned char* tb = nullptr;
    if (OUTMODE == 1)
        tb = (unsigned char*)(Y16 + (size_t)(b * MTILES + blockIdx.x) * 2048);

#pragma unroll
    for (int i = 0; i < 2; i++) {
        int o0 = wm * 32 + i * 16 + (l >> 2);
        float b0v = __ldg(bias + o0);
        float b1v = __ldg(bias + o0 + 8);
#pragma unroll
        for (int j = 0; j < 8; j++) {
            int ml = wn * 64 + j * 8 + (l & 3) * 2;
            int m = m0 + ml;
            size_t p0 = (size_t)o0 * S + m;
            size_t p1 = (size_t)(o0 + 8) * S + m;
            float y0 = d[i][j][0] + b0v, y1 = d[i][j][1] + b0v;
            float y2 = d[i][j][2] + b1v, y3 = d[i][j][3] + b1v;
            if (OUTMODE == 2) {
                float2 a0 = *(const float2*)(Ab + p0);
                float2 a1 = *(const float2*)(Ab + p1);
                y0 += scl * a0.x; y1 += scl * a0.y;
                y2 += scl * a1.x; y3 += scl * a1.y;
            }
            *(float2*)(Yb + p0) = make_float2(y0, y1);
            *(float2*)(Yb + p1) = make_float2(y2, y3);
            if (OUTMODE == 1) {
                *(unsigned*)(tb + sw_off(o0, ml))     = pack_h2(y0, y1);
                *(unsigned*)(tb + sw_off(o0 + 8, ml)) = pack_h2(y2, y3);
            }
        }
    }
}

// ---------------- fused per-(b,t) cross attention (fp32 SIMT) ---------------
// Reads q/k/v fp32; writes attended as fp16sw tiles for the o-projection.
__global__ void __launch_bounds__(256) attn_k(
    const float* __restrict__ Q, const float* __restrict__ Kb,
    const float* __restrict__ Vb, uint4* __restrict__ Att16,
    const float* __restrict__ basis,
    const float* __restrict__ sscaleP, const float* __restrict__ pscaleP)
{
    extern __shared__ float sm[];
    float* Ks = sm;                  // [128][68]
    float* Qs = Ks + 128 * 68;       // [128][68]
    float* Vs = Qs + 128 * 68;       // [128][65]
    float* Ss = Vs + 128 * 65;       // [64][65]
    const int t = blockIdx.x, b = blockIdx.y;
    const int tid = threadIdx.x;
    const float sscale = __ldg(sscaleP), pscale = __ldg(pscaleP);

    for (int lin = tid; lin < 128 * 64; lin += 256) {
        int c = lin >> 6, kk = lin & 63;
        size_t g = ((size_t)(b * 128 + c) * 128 + t) * 64 + kk;
        Ks[c * 68 + kk] = Kb[g];
        Vs[c * 65 + kk] = Vb[g];
    }
    __syncthreads();

    const int ty = tid >> 4, tx = tid & 15;
    const int ay = tid >> 4, ax = tid & 15;

    for (int f0 = 0; f0 < 512; f0 += 64) {
        for (int lin = tid; lin < 128 * 64; lin += 256) {
            int c = lin >> 6, j = lin & 63;
            Qs[c * 68 + j] = Q[((size_t)(b * 128 + c) * 128 + t) * 512 + f0 + j];
        }
        __syncthreads();

        float acc[4][4] = {};
#pragma unroll 4
        for (int c = 0; c < 128; c++) {
            float4 af = *(const float4*)&Qs[c * 68 + ty * 4];
            float4 bf = *(const float4*)&Ks[c * 68 + tx * 4];
            float av[4] = {af.x, af.y, af.z, af.w};
            float bv[4] = {bf.x, bf.y, bf.z, bf.w};
#pragma unroll
            for (int i = 0; i < 4; i++)
#pragma unroll
                for (int j = 0; j < 4; j++)
                    acc[i][j] = fmaf(av[i], bv[j], acc[i][j]);
        }
#pragma unroll
        for (int i = 0; i < 4; i++)
#pragma unroll
            for (int j = 0; j < 4; j++) {
                int fl = ty * 4 + i, kk = tx * 4 + j;
                Ss[fl * 65 + kk] = acc[i][j] * sscale
                                 + pscale * basis[kk * 512 + f0 + fl];
            }
        __syncthreads();

        {
            int row = tid >> 2, q = tid & 3;
            float* rr = &Ss[row * 65];
            float mx = -3.4e38f;
            for (int i = q; i < 64; i += 4) mx = fmaxf(mx, rr[i]);
            mx = fmaxf(mx, __shfl_xor_sync(0xffffffffu, mx, 1));
            mx = fmaxf(mx, __shfl_xor_sync(0xffffffffu, mx, 2));
            float sum = 0.f;
            for (int i = q; i < 64; i += 4) { float e = fast_exp(rr[i] - mx); rr[i] = e; sum += e; }
            sum += __shfl_xor_sync(0xffffffffu, sum, 1);
            sum += __shfl_xor_sync(0xffffffffu, sum, 2);
            float inv = fast_rcp(sum);
            for (int i = q; i < 64; i += 4) rr[i] *= inv;
        }
        __syncthreads();

        float at[8][4] = {};
        for (int kk = 0; kk < 64; kk++) {
            float bv[4];
#pragma unroll
            for (int j = 0; j < 4; j++) bv[j] = Ss[(ax * 4 + j) * 65 + kk];
#pragma unroll
            for (int i = 0; i < 8; i++) {
                float av = Vs[(ay * 8 + i) * 65 + kk];
#pragma unroll
                for (int j = 0; j < 4; j++) at[i][j] = fmaf(av, bv[j], at[i][j]);
            }
        }
        // write attended -> fp16sw tile (consumed by o-projection)
        unsigned char* tb = (unsigned char*)(Att16
            + (size_t)(b * 512 + t * 4 + (f0 >> 7)) * 2048);
        int mb = (f0 & 64) + ax * 4;
#pragma unroll
        for (int i = 0; i < 8; i++) {
            int c = ay * 8 + i;
            *(unsigned*)(tb + sw_off(c, mb))     = pack_h2(at[i][0], at[i][1]);
            *(unsigned*)(tb + sw_off(c, mb + 2)) = pack_h2(at[i][2], at[i][3]);
        }
    }
}

// ---------------- launch ----------------------------------------------------
extern "C" void kernel_launch(void* const* d_in, const int* in_sizes, int n_in,
                              void* d_out, int out_size)
{
    const float* latent     = (const float*)d_in[0];
    const float* side       = (const float*)d_in[1];
    const float* basis      = (const float*)d_in[2];
    const float* lp_gamma   = (const float*)d_in[3];
    const float* lp_w       = (const float*)d_in[4];
    const float* lp_b       = (const float*)d_in[5];
    const float* qn_gamma   = (const float*)d_in[6];
    const float* qmlp_in_w  = (const float*)d_in[7];
    const float* qmlp_in_b  = (const float*)d_in[8];
    const float* qmlp_out_w = (const float*)d_in[9];
    const float* qmlp_out_b = (const float*)d_in[10];
    const float* q_w        = (const float*)d_in[11];
    const float* q_b        = (const float*)d_in[12];
    const float* k_w        = (const float*)d_in[13];
    const float* k_b        = (const float*)d_in[14];
    const float* v_w        = (const float*)d_in[15];
    const float* v_b        = (const float*)d_in[16];
    const float* o_w        = (const float*)d_in[17];
    const float* o_b        = (const float*)d_in[18];
    const float* ffn_gamma  = (const float*)d_in[19];
    const float* ffn_in_w   = (const float*)d_in[20];
    const float* ffn_in_b   = (const float*)d_in[21];
    const float* ffn_out_w  = (const float*)d_in[22];
    const float* ffn_out_b  = (const float*)d_in[23];
    const float* score_scale      = (const float*)d_in[24];
    const float* prior_scale      = (const float*)d_in[25];
    const float* query_skip_scale = (const float*)d_in[26];
    float* out = (float*)d_out;

    float *kbuf_p, *vbuf_p, *qh_p, *q_p;
    uint4 *lat16, *A16, *qh16, *att16, *wfrag;
    cudaGetSymbolAddress((void**)&kbuf_p, g_kbuf);
    cudaGetSymbolAddress((void**)&vbuf_p, g_vbuf);
    cudaGetSymbolAddress((void**)&qh_p,   g_qh);
    cudaGetSymbolAddress((void**)&q_p,    g_q);
    cudaGetSymbolAddress((void**)&lat16,  g_lat16);
    cudaGetSymbolAddress((void**)&A16,    g_A16);
    cudaGetSymbolAddress((void**)&qh16,   g_qh16);
    cudaGetSymbolAddress((void**)&att16,  g_att16);
    cudaGetSymbolAddress((void**)&wfrag,  g_Wp);

    const int OFF_LP = 0, OFF_QIN = 64, OFF_QOUT = 192, OFF_Q = 256,
              OFF_K = 320, OFF_V = 384, OFF_O = 448, OFF_FIN = 512, OFF_FOUT = 640;

    WPtrs wp;
    wp.p[0] = lp_w;      wp.p[1] = qmlp_in_w; wp.p[2] = qmlp_out_w;
    wp.p[3] = q_w;       wp.p[4] = k_w;       wp.p[5] = v_w;
    wp.p[6] = o_w;       wp.p[7] = ffn_in_w;  wp.p[8] = ffn_out_w;
    prep_all<<<88, 256>>>(wp, wfrag);

    // latent path: rmsnorm -> lp conv -> silu -> lat16
    gemm_f32in<128><<<dim3(SL / 128, 1, 8), 256>>>(
        wfrag + OFF_LP * 32, lp_b, latent, lp_gamma, lat16, SL);
    // k, v projections (fp16sw in, fp32 out for attention)
    gemm_h16<0><<<dim3(SL / 128, 1, 8), 256>>>(
        wfrag + OFF_K * 32, k_b, lat16, SL >> 7, kbuf_p, nullptr, nullptr, nullptr, SL);
    gemm_h16<0><<<dim3(SL / 128, 1, 8), 256>>>(
        wfrag + OFF_V * 32, v_b, lat16, SL >> 7, vbuf_p, nullptr, nullptr, nullptr, SL);

    // side path: rmsnorm -> qmlp_in -> GLU (in epilogue) -> A16
    gemm_f32in<256><<<dim3(SS / 64, 1, 8), 256>>>(
        wfrag + OFF_QIN * 32, qmlp_in_b, side, qn_gamma, A16, SS);
    // qmlp_out: A16 -> qh fp32 (for skip) + qh16 (for q proj)
    gemm_h16<1><<<dim3(SS / 128, 1, 8), 256>>>(
        wfrag + OFF_QOUT * 32, qmlp_out_b, A16, SS >> 7, qh_p, qh16, nullptr, nullptr, SS);
    // q projection: qh16 -> q fp32
    gemm_h16<0><<<dim3(SS / 128, 1, 8), 256>>>(
        wfrag + OFF_Q * 32, q_b, qh16, SS >> 7, q_p, nullptr, nullptr, nullptr, SS);

    // fused attention -> att16
    cudaFuncSetAttribute(attn_k, cudaFuncAttributeMaxDynamicSharedMemorySize, 119552);
    attn_k<<<dim3(128, 8), 256, 119552>>>(q_p, kbuf_p, vbuf_p, att16, basis,
                                          score_scale, prior_scale);

    // o projection + query skip -> hidden (d_out)
    gemm_h16<2><<<dim3(SS / 128, 1, 8), 256>>>(
        wfrag + OFF_O * 32, o_b, att16, SS >> 7, out, nullptr,
        qh_p, query_skip_scale, SS);

    // ffn: rmsnorm -> ffn_in -> GLU (in epilogue) -> A16
    gemm_f32in<256><<<dim3(SS / 64, 1, 8), 256>>>(
        wfrag + OFF_FIN * 32, ffn_in_b, out, ffn_gamma, A16, SS);
    // ffn_out + residual -> hidden (d_out)
    gemm_h16<2><<<dim3(SS / 128, 1, 8), 256>>>(
        wfrag + OFF_FOUT * 32, ffn_out_b, A16, SS >> 7, out, nullptr,
        out, nullptr, SS);
}